// round 11
// baseline (speedup 1.0000x reference)
#include <cuda_runtime.h>

// Single persistent kernel: sampled radix-select threshold + fused mask.
// Grid-wide sense barrier (co-residency guaranteed via occupancy API).
// Key map (order-preserving): neg -> ~bits, pos -> bits|0x80000000.

#define BLOCK     256
#define MAXG      2048
#define REP       8
#define STAGE_CAP 2048
#define CAND_CAP  (1u << 22)
#define MARGIN    3000u
#define MAX_EXP   15

static __device__ unsigned g_shist[REP * 65536];  // replicated sample hist
static __device__ unsigned g_part[MAXG];          // per-block slice partials
static __device__ unsigned g_hist2048[2048];      // level-1 candidate hist
static __device__ unsigned g_hist2b[2048];        // level-2 candidate hist
static __device__ unsigned g_hist64k[65536];      // fallback-only hist
static __device__ unsigned g_below, g_count, g_overflow, g_fail;
static __device__ float    g_threshold;
static __device__ unsigned g_bar_count, g_bar_gen;
static __device__ unsigned g_cand[CAND_CAP];
static __device__ unsigned g_cidx[CAND_CAP];

__device__ __forceinline__ unsigned f2key(float f) {
    unsigned u = __float_as_uint(f);
    return (u & 0x80000000u) ? ~u : (u | 0x80000000u);
}
__device__ __forceinline__ float key2f(unsigned key) {
    unsigned u = (key & 0x80000000u) ? (key & 0x7fffffffu) : ~key;
    return __uint_as_float(u);
}

// Grid barrier: sync-then-elect arrive; release via gen bump; volatile spin.
__device__ __forceinline__ void gsync(int G) {
    __syncthreads();
    if (threadIdx.x == 0) {
        __threadfence();
        unsigned gen = *(volatile unsigned*)&g_bar_gen;
        if (atomicAdd(&g_bar_count, 1u) == (unsigned)G - 1u) {
            g_bar_count = 0u;
            __threadfence();
            atomicAdd(&g_bar_gen, 1u);
        } else {
            while (*(volatile unsigned*)&g_bar_gen == gen) __nanosleep(64);
        }
        __threadfence();
    }
    __syncthreads();
}

// Block-parallel rank-select over smem hist (nb <= 2048, blockDim 256).
// Caller inits *o_bin = ~0u (+sync) before; ends with syncthreads.
__device__ __forceinline__ void bsel(const unsigned* h, int nb, unsigned target,
                                     unsigned* o_bin, unsigned* o_rank,
                                     unsigned* s_wofs) {
    int tid = threadIdx.x, lane = tid & 31, wid = tid >> 5;
    int C = (nb + BLOCK - 1) / BLOCK;
    int base = tid * C;
    unsigned my = 0u;
    for (int j = 0; j < C; j++) { int b = base + j; if (b < nb) my += h[b]; }
    unsigned v = my;
#pragma unroll
    for (int off = 1; off < 32; off <<= 1) {
        unsigned t = __shfl_up_sync(0xffffffffu, v, off);
        if (lane >= off) v += t;
    }
    if (lane == 31) s_wofs[wid + 1] = v;
    if (tid == 0) s_wofs[0] = 0u;
    __syncthreads();
    if (tid == 0) for (int w = 1; w <= 8; w++) s_wofs[w] += s_wofs[w - 1];
    __syncthreads();
    unsigned excl = s_wofs[wid] + v - my;
    if (my && target >= excl && target < excl + my) {
        unsigned cum = excl;
        for (int j = 0; j < C; j++) {
            int b = base + j; if (b >= nb) break;
            unsigned c = h[b];
            if (target < cum + c) { *o_bin = (unsigned)b; *o_rank = target - cum; break; }
            cum += c;
        }
    }
    __syncthreads();
}

__global__ __launch_bounds__(BLOCK, 8)
void k_fused(const float4* __restrict__ x4, int n4,
             const float* __restrict__ x, int n,
             float* __restrict__ out, unsigned idx, unsigned t_target, int G) {
    __shared__ unsigned s_a[2048];       // pick: slice | main: cand keys | D: lvl2 hist
    __shared__ unsigned s_b[2048];       // pick: window | main: cand idx
    __shared__ unsigned s_h[2048];       // staging: partials/hists | main: lvl1 hist
    __shared__ unsigned s_wofs[9];
    __shared__ unsigned s_obin, s_orank, s_cnt, s_below, s_base;
    __shared__ unsigned s_klo, s_shift, s_pickok;
    __shared__ float    s_flo, s_fhi;
    const int tid = threadIdx.x;
    const int bid = blockIdx.x;
    const int gstride = G * BLOCK;

    if (bid == 0 && tid == 0) g_fail = 0u;   // prev replay's fallback is done

    // ---- Phase A: coalesced sampling (first 32 float4s of each 1024 chunk) ----
    {
        const unsigned rbase = (unsigned)(bid & (REP - 1)) * 65536u;
        const int nchunks = (n4 + 1023) / 1024;
        for (int t = bid * BLOCK + tid; t < nchunks * 32; t += gstride) {
            int i = (t >> 5) * 1024 + (t & 31);
            if (i < n4) {
                float4 v = __ldg(&x4[i]);
                atomicAdd(&g_shist[rbase + (f2key(v.x) >> 16)], 1u);
                atomicAdd(&g_shist[rbase + (f2key(v.y) >> 16)], 1u);
                atomicAdd(&g_shist[rbase + (f2key(v.z) >> 16)], 1u);
                atomicAdd(&g_shist[rbase + (f2key(v.w) >> 16)], 1u);
            }
        }
    }
    gsync(G);

    // ---- Phase B: per-block slice partial sums ----
    const int SLICE = (65536 + G - 1) / G;
    {
        int base = bid * SLICE;
        unsigned sum = 0u;
        for (int i = tid; i < SLICE; i += BLOCK) {
            int b = base + i;
            if (b < 65536) {
                unsigned s = 0u;
#pragma unroll
                for (int r = 0; r < REP; r++) s += g_shist[r * 65536 + b];
                sum += s;
            }
        }
#pragma unroll
        for (int off = 16; off > 0; off >>= 1)
            sum += __shfl_down_sync(0xffffffffu, sum, off);
        if ((tid & 31) == 0) s_wofs[tid >> 5] = sum;
        __syncthreads();
        if (tid == 0) {
            unsigned t = 0u;
            for (int w = 0; w < 8; w++) t += s_wofs[w];
            g_part[bid] = t;
        }
        __syncthreads();
    }
    gsync(G);

    // ---- Phase C1: every block computes the SAME pick locally ----
    {
        for (int i = tid; i < G; i += BLOCK) s_h[i] = g_part[i];
        if (tid == 0) { s_obin = 0xffffffffu; s_pickok = 0u; }
        __syncthreads();
        bsel(s_h, G, t_target, &s_obin, &s_orank, s_wofs);
        int seg = (int)s_obin;
        unsigned segrank = s_orank;
        if (seg != -1) {
            int base = seg * SLICE;
            int nb = 65536 - base; if (nb > SLICE) nb = SLICE;
            for (int i = tid; i < nb; i += BLOCK) {
                unsigned s = 0u;
#pragma unroll
                for (int r = 0; r < REP; r++) s += g_shist[r * 65536 + base + i];
                s_a[i] = s;
            }
            if (tid == 0) s_obin = 0xffffffffu;
            __syncthreads();
            bsel(s_a, nb, segrank, &s_obin, &s_orank, s_wofs);
            int bc = (s_obin == 0xffffffffu) ? -1 : base + (int)s_obin;
            if (bc >= 0) {
                int w0 = bc - 16;
                for (int i = tid; i < 33; i += BLOCK) {
                    int b = w0 + i;
                    unsigned s = 0u;
                    if (b >= 0 && b < 65536) {
#pragma unroll
                        for (int r = 0; r < REP; r++) s += g_shist[r * 65536 + b];
                    }
                    s_b[i] = s;
                }
                __syncthreads();
                if (tid == 0) {
                    int lo = 16; unsigned accL = 0u;
                    while ((w0 + lo) > 0 && accL < MARGIN && (16 - lo) < MAX_EXP) { lo--; accL += s_b[lo]; }
                    int hi = 16; unsigned accR = 0u;
                    while ((w0 + hi) < 65535 && accR < MARGIN && (hi - 16) < MAX_EXP) { hi++; accR += s_b[hi]; }
                    int lob = w0 + lo, hib = w0 + hi;
                    if (lob == 0x8000) lob--;
                    if (hib == 0x7fff) hib++;
                    if (lob < 0) lob = 0;
                    if (hib > 65535) hib = 65535;
                    unsigned klo = (unsigned)lob << 16;
                    unsigned khi = ((unsigned)hib << 16) | 0xffffu;
                    unsigned range = khi - klo, sh = 0u;
                    while ((range >> sh) >= 2048u) sh++;
                    s_klo = klo; s_shift = sh;
                    s_flo = key2f(klo); s_fhi = key2f(khi);
                    s_pickok = 1u;
                }
            }
        }
        __syncthreads();
        if (!s_pickok && tid == 0) { s_flo = 1.0f; s_fhi = 0.0f; s_klo = 0u; s_shift = 0u; }
        __syncthreads();
    }

    // ---- Phase C2: main fused pass (2x batched loads; lean for 32 regs) ----
    const float flo = s_flo, fhi = s_fhi;
    const unsigned klo = s_klo, sh = s_shift;
    const unsigned pickok = s_pickok;
    __syncthreads();   // C1's s_b window walk done before s_b reuse below
    {
        for (int i = tid; i < 2048; i += BLOCK) s_h[i] = 0u;
        if (tid == 0) { s_cnt = 0u; s_below = 0u; }
        __syncthreads();
        unsigned below = 0u;
        float4* o4 = (float4*)out;
        int i = bid * BLOCK + tid;
        for (; i + gstride < n4; i += 2 * gstride) {
            float4 v0 = __ldcs(&x4[i]);
            float4 v1 = __ldcs(&x4[i + gstride]);
            float4 r0, r1;
            r0.x = (v0.x > fhi) ? 1.0f : 0.0f; r0.y = (v0.y > fhi) ? 1.0f : 0.0f;
            r0.z = (v0.z > fhi) ? 1.0f : 0.0f; r0.w = (v0.w > fhi) ? 1.0f : 0.0f;
            r1.x = (v1.x > fhi) ? 1.0f : 0.0f; r1.y = (v1.y > fhi) ? 1.0f : 0.0f;
            r1.z = (v1.z > fhi) ? 1.0f : 0.0f; r1.w = (v1.w > fhi) ? 1.0f : 0.0f;
            __stcs(&o4[i], r0);
            __stcs(&o4[i + gstride], r1);
            below += (v0.x < flo) + (v0.y < flo) + (v0.z < flo) + (v0.w < flo);
            below += (v1.x < flo) + (v1.y < flo) + (v1.z < flo) + (v1.w < flo);
            bool c0 = (v0.x >= flo && v0.x <= fhi) || (v0.y >= flo && v0.y <= fhi) ||
                      (v0.z >= flo && v0.z <= fhi) || (v0.w >= flo && v0.w <= fhi);
            bool c1 = (v1.x >= flo && v1.x <= fhi) || (v1.y >= flo && v1.y <= fhi) ||
                      (v1.z >= flo && v1.z <= fhi) || (v1.w >= flo && v1.w <= fhi);
            unsigned am = __activemask();
            if (__ballot_sync(am, c0 || c1)) {
#pragma unroll
                for (int u = 0; u < 2; u++) {
                    float4 v = (u == 0) ? v0 : v1;
                    unsigned e = (unsigned)(i + u * gstride) * 4u;
                    if (v.x >= flo && v.x <= fhi) {
                        unsigned key = f2key(v.x);
                        unsigned p = atomicAdd(&s_cnt, 1u);
                        if (p < STAGE_CAP) { s_a[p] = key; s_b[p] = e; atomicAdd(&s_h[min((key - klo) >> sh, 2047u)], 1u); }
                    }
                    if (v.y >= flo && v.y <= fhi) {
                        unsigned key = f2key(v.y);
                        unsigned p = atomicAdd(&s_cnt, 1u);
                        if (p < STAGE_CAP) { s_a[p] = key; s_b[p] = e + 1u; atomicAdd(&s_h[min((key - klo) >> sh, 2047u)], 1u); }
                    }
                    if (v.z >= flo && v.z <= fhi) {
                        unsigned key = f2key(v.z);
                        unsigned p = atomicAdd(&s_cnt, 1u);
                        if (p < STAGE_CAP) { s_a[p] = key; s_b[p] = e + 2u; atomicAdd(&s_h[min((key - klo) >> sh, 2047u)], 1u); }
                    }
                    if (v.w >= flo && v.w <= fhi) {
                        unsigned key = f2key(v.w);
                        unsigned p = atomicAdd(&s_cnt, 1u);
                        if (p < STAGE_CAP) { s_a[p] = key; s_b[p] = e + 3u; atomicAdd(&s_h[min((key - klo) >> sh, 2047u)], 1u); }
                    }
                }
            }
        }
        for (; i < n4; i += gstride) {
            float4 v = __ldcs(&x4[i]);
            float4 rr;
            rr.x = (v.x > fhi) ? 1.0f : 0.0f;
            rr.y = (v.y > fhi) ? 1.0f : 0.0f;
            rr.z = (v.z > fhi) ? 1.0f : 0.0f;
            rr.w = (v.w > fhi) ? 1.0f : 0.0f;
            __stcs(&o4[i], rr);
            below += (v.x < flo) + (v.y < flo) + (v.z < flo) + (v.w < flo);
            unsigned e = (unsigned)i * 4u;
            if (v.x >= flo && v.x <= fhi) {
                unsigned key = f2key(v.x);
                unsigned p = atomicAdd(&s_cnt, 1u);
                if (p < STAGE_CAP) { s_a[p] = key; s_b[p] = e; atomicAdd(&s_h[min((key - klo) >> sh, 2047u)], 1u); }
            }
            if (v.y >= flo && v.y <= fhi) {
                unsigned key = f2key(v.y);
                unsigned p = atomicAdd(&s_cnt, 1u);
                if (p < STAGE_CAP) { s_a[p] = key; s_b[p] = e + 1u; atomicAdd(&s_h[min((key - klo) >> sh, 2047u)], 1u); }
            }
            if (v.z >= flo && v.z <= fhi) {
                unsigned key = f2key(v.z);
                unsigned p = atomicAdd(&s_cnt, 1u);
                if (p < STAGE_CAP) { s_a[p] = key; s_b[p] = e + 2u; atomicAdd(&s_h[min((key - klo) >> sh, 2047u)], 1u); }
            }
            if (v.w >= flo && v.w <= fhi) {
                unsigned key = f2key(v.w);
                unsigned p = atomicAdd(&s_cnt, 1u);
                if (p < STAGE_CAP) { s_a[p] = key; s_b[p] = e + 3u; atomicAdd(&s_h[min((key - klo) >> sh, 2047u)], 1u); }
            }
        }
#pragma unroll
        for (int off = 16; off > 0; off >>= 1)
            below += __shfl_down_sync(0xffffffffu, below, off);
        if ((tid & 31) == 0) atomicAdd(&s_below, below);
        __syncthreads();
        unsigned cnt = s_cnt < STAGE_CAP ? s_cnt : STAGE_CAP;
        if (tid == 0) {
            if (s_cnt > STAGE_CAP) atomicExch(&g_overflow, 1u);
            atomicAdd(&g_below, s_below);
            s_base = atomicAdd(&g_count, cnt);
        }
        __syncthreads();
        unsigned base = s_base;
        for (unsigned j = tid; j < cnt; j += BLOCK) {
            g_cand[base + j] = s_a[j];
            g_cidx[base + j] = s_b[j];
        }
        for (int j = tid; j < 2048; j += BLOCK)
            if (s_h[j]) atomicAdd(&g_hist2048[j], s_h[j]);
        // scalar tail (n % 4), block 0 only
        if (bid == 0) {
            for (int j = (n & ~3) + tid; j < n; j += BLOCK) {
                float v = x[j];
                out[j] = (v > fhi) ? 1.0f : 0.0f;
                if (v < flo) atomicAdd(&g_below, 1u);
                else if (v >= flo && v <= fhi) {
                    unsigned key = f2key(v);
                    unsigned p = atomicAdd(&g_count, 1u);
                    if (p < CAND_CAP) {
                        g_cand[p] = key; g_cidx[p] = (unsigned)j;
                        atomicAdd(&g_hist2048[min((key - klo) >> sh, 2047u)], 1u);
                    } else atomicExch(&g_overflow, 1u);
                }
            }
        }
    }
    gsync(G);

    // ---- Phase D: level-1 select (local) + level-2 candidate hist ----
    unsigned nc, ok, b2base = 0u, rank2 = 0u, w = 1u;
    {
        for (int i = tid; i < 2048; i += BLOCK) s_h[i] = g_hist2048[i];
        unsigned below_g = g_below;
        nc = g_count;
        unsigned ovf = g_overflow;
        ok = pickok && (!ovf) && (idx >= below_g) && ((idx - below_g) < nc) && (nc <= CAND_CAP);
        if (tid == 0) s_obin = 0xffffffffu;
        __syncthreads();
        if (ok) {
            bsel(s_h, 2048, idx - below_g, &s_obin, &s_orank, s_wofs);
            if (s_obin == 0xffffffffu) ok = 0u;
            else {
                b2base = klo + (s_obin << sh);
                rank2 = s_orank;
                w = 1u << sh;
                for (int i = tid; i < 2048; i += BLOCK) s_a[i] = 0u;
                __syncthreads();
                for (unsigned i = bid * BLOCK + tid; i < nc; i += (unsigned)gstride) {
                    unsigned off = g_cand[i] - b2base;
                    if (off < w) atomicAdd(&s_a[min(off, 2047u)], 1u);
                }
                __syncthreads();
                unsigned wcap = w < 2048u ? w : 2048u;
                for (unsigned i = tid; i < wcap; i += BLOCK)
                    if (s_a[i]) atomicAdd(&g_hist2b[i], s_a[i]);
            }
        }
        // zero sample hist slice + partials (last read in phase C1)
        int base = bid * SLICE;
        for (int i = tid; i < SLICE; i += BLOCK) {
            int b = base + i;
            if (b < 65536) {
#pragma unroll
                for (int r = 0; r < REP; r++) g_shist[r * 65536 + b] = 0u;
            }
        }
        if (tid == 0) g_part[bid] = 0u;
    }
    gsync(G);

    // ---- Phase E: threshold select (local) + cleanup + fixup ----
    {
        for (int i = tid; i < 2048; i += BLOCK) s_h[i] = g_hist2b[i];
        if (tid == 0) s_obin = 0xffffffffu;
        __syncthreads();
        float thr = __int_as_float(0x7f800000);
        if (ok) {
            int nb = (int)(w < 2048u ? w : 2048u);
            bsel(s_h, nb, rank2, &s_obin, &s_orank, s_wofs);
            if (s_obin == 0xffffffffu) ok = 0u;
            else thr = key2f(b2base + s_obin);
        }
        gsync(G);
        // cleanup (everyone staged what they need)
        for (int i = bid * BLOCK + tid; i < 2048; i += gstride) {
            g_hist2048[i] = 0u;
            g_hist2b[i] = 0u;
        }
        if (bid == 0 && tid == 0) {
            g_below = 0u; g_count = 0u; g_overflow = 0u;
            if (!ok) g_fail = 1u;
            else g_threshold = thr;
        }
        if (ok) {
            for (unsigned i = bid * BLOCK + tid; i < nc; i += (unsigned)gstride)
                if (key2f(g_cand[i]) >= thr) out[g_cidx[i]] = 1.0f;
        }
    }
}

// ---------------- fallback: exact 2-pass 16-bit radix, one block ------------
__global__ void f_all(const float* __restrict__ x, int n, unsigned idx) {
    if (!g_fail) return;
    __shared__ unsigned s_part[1024];
    __shared__ int s_seg;
    __shared__ unsigned s_segexcl, s_fb, s_fr;
    int tid = threadIdx.x;
    for (int b = tid; b < 65536; b += 1024) g_hist64k[b] = 0u;
    __syncthreads();
    for (int i = tid; i < n; i += blockDim.x)
        atomicAdd(&g_hist64k[f2key(x[i]) >> 16], 1u);
    __syncthreads();
    for (int phase = 0; phase < 2; phase++) {
        unsigned target = (phase == 0) ? idx : s_fr;
        if (tid == 0) s_seg = -1;
        unsigned my = 0u;
        for (int b = tid * 64; b < tid * 64 + 64; b++) my += g_hist64k[b];
        s_part[tid] = my;
        __syncthreads();
        for (int off = 1; off < 1024; off <<= 1) {
            unsigned t = (tid >= off) ? s_part[tid - off] : 0u;
            __syncthreads();
            s_part[tid] += t;
            __syncthreads();
        }
        unsigned incl = s_part[tid], excl = incl - my;
        if (my && target >= excl && target < incl) { s_seg = tid; s_segexcl = excl; }
        __syncthreads();
        if (tid == 0 && s_seg >= 0) {
            unsigned cum = s_segexcl;
            for (int b = s_seg * 64; b < s_seg * 64 + 64; b++) {
                unsigned c = g_hist64k[b];
                if (target >= cum && target < cum + c) {
                    if (phase == 0) { s_fb = (unsigned)b; s_fr = target - cum; }
                    else g_threshold = key2f((s_fb << 16) | (unsigned)b);
                    break;
                }
                cum += c;
            }
        }
        __syncthreads();
        for (int b = tid; b < 65536; b += 1024) g_hist64k[b] = 0u;
        __syncthreads();
        if (phase == 0) {
            unsigned fb = s_fb;
            for (int i = tid; i < n; i += blockDim.x) {
                unsigned key = f2key(x[i]);
                if ((key >> 16) == fb) atomicAdd(&g_hist64k[key & 0xffffu], 1u);
            }
            __syncthreads();
        }
    }
}

__global__ void f_mask(const float* __restrict__ x, float* __restrict__ out, int n) {
    if (!g_fail) return;
    const float thr = g_threshold;
    const int stride = gridDim.x * blockDim.x;
    for (int i = blockIdx.x * blockDim.x + threadIdx.x; i < n; i += stride)
        out[i] = (x[i] >= thr) ? 1.0f : 0.0f;
}

__global__ void k_fill0(float* __restrict__ out, int n) {
    const int stride = gridDim.x * blockDim.x;
    for (int i = blockIdx.x * blockDim.x + threadIdx.x; i < n; i += stride)
        out[i] = 0.0f;
}

extern "C" void kernel_launch(void* const* d_in, const int* in_sizes, int n_in,
                              void* d_out, int out_size) {
    const float* x = (const float*)d_in[0];
    float* out = (float*)d_out;
    const long long n = (long long)in_sizes[0];
    const long long k = (long long)((double)n * 0.9);
    if (k <= 0) { k_fill0<<<1184, 256>>>(out, (int)n); return; }
    const unsigned idx = (unsigned)(n - k);   // 0-indexed ascending rank
    const int n4 = (int)(n >> 2);
    // sampled count: first 32 float4s of each 1024-float4 chunk
    const long long full = n4 / 1024, rem = n4 % 1024;
    const long long m4 = full * 32 + (rem < 32 ? rem : 32);
    const long long m = m4 * 4;
    unsigned t_target = 0u;
    if (m > 0) {
        t_target = (unsigned)((double)idx * (double)m / (double)n);
        if (t_target >= (unsigned)m) t_target = (unsigned)m - 1u;
    }

    int sm = 148, occ = 8, dev = 0;
    cudaGetDevice(&dev);
    cudaDeviceGetAttribute(&sm, cudaDevAttrMultiProcessorCount, dev);
    cudaOccupancyMaxActiveBlocksPerMultiprocessor(&occ, k_fused, BLOCK, 0);
    if (occ > 8) occ = 8;
    if (occ < 1) occ = 1;
    int G = sm * occ;
    if (G > MAXG) G = MAXG;
    if (G < 1) G = 1;

    k_fused<<<G, BLOCK>>>((const float4*)x, n4, x, (int)n, out, idx, t_target, G);
    // fallback (no-ops unless g_fail)
    f_all<<<1, 1024>>>(x, (int)n, idx);
    f_mask<<<1184, 256>>>(x, out, (int)n);
}

// round 12
// speedup vs baseline: 1.1440x; 1.1440x over previous
#include <cuda_runtime.h>

// Single persistent kernel: sampled radix-select threshold + fused mask,
// with the exact-radix fallback folded in as gated phases (single launch).
// Grid-wide sense barrier (co-residency guaranteed via occupancy API).
// Key map (order-preserving): neg -> ~bits, pos -> bits|0x80000000.

#define BLOCK     256
#define MAXG      2048
#define REP       8
#define STAGE_CAP 2048
#define CAND_CAP  (1u << 22)
#define MARGIN    3000u
#define MAX_EXP   15

static __device__ unsigned g_shist[REP * 65536];  // replicated sample hist
static __device__ unsigned g_part[MAXG];          // per-block slice partials
static __device__ unsigned g_hist2048[2048];      // level-1 candidate hist
static __device__ unsigned g_hist2b[2048];        // level-2 candidate hist
static __device__ unsigned g_hist64k[65536];      // fallback-only hist
static __device__ unsigned g_below, g_count, g_overflow;
static __device__ unsigned g_bar_count, g_bar_gen;
static __device__ unsigned g_cand[CAND_CAP];
static __device__ unsigned g_cidx[CAND_CAP];

__device__ __forceinline__ unsigned f2key(float f) {
    unsigned u = __float_as_uint(f);
    return (u & 0x80000000u) ? ~u : (u | 0x80000000u);
}
__device__ __forceinline__ float key2f(unsigned key) {
    unsigned u = (key & 0x80000000u) ? (key & 0x7fffffffu) : ~key;
    return __uint_as_float(u);
}

// Grid barrier: sync-then-elect arrive; release via gen bump; volatile spin.
__device__ __forceinline__ void gsync(int G) {
    __syncthreads();
    if (threadIdx.x == 0) {
        __threadfence();
        unsigned gen = *(volatile unsigned*)&g_bar_gen;
        if (atomicAdd(&g_bar_count, 1u) == (unsigned)G - 1u) {
            g_bar_count = 0u;
            __threadfence();
            atomicAdd(&g_bar_gen, 1u);
        } else {
            while (*(volatile unsigned*)&g_bar_gen == gen) __nanosleep(64);
        }
        __threadfence();
    }
    __syncthreads();
}

// Block-parallel rank-select over smem hist (nb <= 2048, blockDim 256).
// Caller inits *o_bin = ~0u (+sync) before; ends with syncthreads.
__device__ __forceinline__ void bsel(const unsigned* h, int nb, unsigned target,
                                     unsigned* o_bin, unsigned* o_rank,
                                     unsigned* s_wofs) {
    int tid = threadIdx.x, lane = tid & 31, wid = tid >> 5;
    int C = (nb + BLOCK - 1) / BLOCK;
    int base = tid * C;
    unsigned my = 0u;
    for (int j = 0; j < C; j++) { int b = base + j; if (b < nb) my += h[b]; }
    unsigned v = my;
#pragma unroll
    for (int off = 1; off < 32; off <<= 1) {
        unsigned t = __shfl_up_sync(0xffffffffu, v, off);
        if (lane >= off) v += t;
    }
    if (lane == 31) s_wofs[wid + 1] = v;
    if (tid == 0) s_wofs[0] = 0u;
    __syncthreads();
    if (tid == 0) for (int w = 1; w <= 8; w++) s_wofs[w] += s_wofs[w - 1];
    __syncthreads();
    unsigned excl = s_wofs[wid] + v - my;
    if (my && target >= excl && target < excl + my) {
        unsigned cum = excl;
        for (int j = 0; j < C; j++) {
            int b = base + j; if (b >= nb) break;
            unsigned c = h[b];
            if (target < cum + c) { *o_bin = (unsigned)b; *o_rank = target - cum; break; }
            cum += c;
        }
    }
    __syncthreads();
}

// Two-level block-local select over the 64K global hist (fallback path).
// Every block computes the same (bin, rank) deterministically.
__device__ __forceinline__ void sel64k(const unsigned* gh, unsigned target,
                                       unsigned* o_bin, unsigned* o_rank,
                                       unsigned* s_h, unsigned* s_a,
                                       unsigned* s_wofs,
                                       unsigned* s_obin, unsigned* s_orank) {
    int tid = threadIdx.x;
    for (int g = tid; g < 1024; g += BLOCK) {
        unsigned s = 0u;
        for (int j = 0; j < 64; j++) s += gh[g * 64 + j];
        s_h[g] = s;
    }
    if (tid == 0) *s_obin = 0xffffffffu;
    __syncthreads();
    bsel(s_h, 1024, target, s_obin, s_orank, s_wofs);
    unsigned grp = *s_obin, grank = *s_orank;
    *o_bin = 0xffffffffu;
    if (grp != 0xffffffffu) {
        for (int j = tid; j < 64; j += BLOCK) s_a[j] = gh[grp * 64 + j];
        if (tid == 0) *s_obin = 0xffffffffu;
        __syncthreads();
        bsel(s_a, 64, grank, s_obin, s_orank, s_wofs);
        if (*s_obin != 0xffffffffu) {
            *o_bin = grp * 64u + *s_obin;
            *o_rank = *s_orank;
        }
    }
    __syncthreads();
}

__global__ __launch_bounds__(BLOCK, 6)
void k_fused(const float4* __restrict__ x4, int n4,
             const float* __restrict__ x, int n,
             float* __restrict__ out, unsigned idx, unsigned t_target, int G) {
    __shared__ unsigned s_a[2048];       // pick: slice | main: cand keys | D: lvl2 hist
    __shared__ unsigned s_b[2048];       // pick: window | main: cand idx
    __shared__ unsigned s_h[2048];       // staging: partials/hists | main: lvl1 hist
    __shared__ unsigned s_wofs[9];
    __shared__ unsigned s_obin, s_orank, s_cnt, s_below, s_base;
    __shared__ unsigned s_klo, s_shift, s_pickok;
    __shared__ float    s_flo, s_fhi;
    const int tid = threadIdx.x;
    const int bid = blockIdx.x;
    const int gstride = G * BLOCK;

    // ---- Phase A: coalesced sampling (first 32 float4s of each 1024 chunk) ----
    {
        const unsigned rbase = (unsigned)(bid & (REP - 1)) * 65536u;
        const int nchunks = (n4 + 1023) / 1024;
        for (int t = bid * BLOCK + tid; t < nchunks * 32; t += gstride) {
            int i = (t >> 5) * 1024 + (t & 31);
            if (i < n4) {
                float4 v = __ldg(&x4[i]);
                atomicAdd(&g_shist[rbase + (f2key(v.x) >> 16)], 1u);
                atomicAdd(&g_shist[rbase + (f2key(v.y) >> 16)], 1u);
                atomicAdd(&g_shist[rbase + (f2key(v.z) >> 16)], 1u);
                atomicAdd(&g_shist[rbase + (f2key(v.w) >> 16)], 1u);
            }
        }
    }
    gsync(G);

    // ---- Phase B: per-block slice partial sums ----
    const int SLICE = (65536 + G - 1) / G;
    {
        int base = bid * SLICE;
        unsigned sum = 0u;
        for (int i = tid; i < SLICE; i += BLOCK) {
            int b = base + i;
            if (b < 65536) {
                unsigned s = 0u;
#pragma unroll
                for (int r = 0; r < REP; r++) s += g_shist[r * 65536 + b];
                sum += s;
            }
        }
#pragma unroll
        for (int off = 16; off > 0; off >>= 1)
            sum += __shfl_down_sync(0xffffffffu, sum, off);
        if ((tid & 31) == 0) s_wofs[tid >> 5] = sum;
        __syncthreads();
        if (tid == 0) {
            unsigned t = 0u;
            for (int w = 0; w < 8; w++) t += s_wofs[w];
            g_part[bid] = t;
        }
        __syncthreads();
    }
    gsync(G);

    // ---- Phase C1: every block computes the SAME pick locally ----
    {
        for (int i = tid; i < G; i += BLOCK) s_h[i] = g_part[i];
        if (tid == 0) { s_obin = 0xffffffffu; s_pickok = 0u; }
        __syncthreads();
        bsel(s_h, G, t_target, &s_obin, &s_orank, s_wofs);
        int seg = (int)s_obin;
        unsigned segrank = s_orank;
        if (seg != -1) {
            int base = seg * SLICE;
            int nb = 65536 - base; if (nb > SLICE) nb = SLICE;
            for (int i = tid; i < nb; i += BLOCK) {
                unsigned s = 0u;
#pragma unroll
                for (int r = 0; r < REP; r++) s += g_shist[r * 65536 + base + i];
                s_a[i] = s;
            }
            if (tid == 0) s_obin = 0xffffffffu;
            __syncthreads();
            bsel(s_a, nb, segrank, &s_obin, &s_orank, s_wofs);
            int bc = (s_obin == 0xffffffffu) ? -1 : base + (int)s_obin;
            if (bc >= 0) {
                int w0 = bc - 16;
                for (int i = tid; i < 33; i += BLOCK) {
                    int b = w0 + i;
                    unsigned s = 0u;
                    if (b >= 0 && b < 65536) {
#pragma unroll
                        for (int r = 0; r < REP; r++) s += g_shist[r * 65536 + b];
                    }
                    s_b[i] = s;
                }
                __syncthreads();
                if (tid == 0) {
                    int lo = 16; unsigned accL = 0u;
                    while ((w0 + lo) > 0 && accL < MARGIN && (16 - lo) < MAX_EXP) { lo--; accL += s_b[lo]; }
                    int hi = 16; unsigned accR = 0u;
                    while ((w0 + hi) < 65535 && accR < MARGIN && (hi - 16) < MAX_EXP) { hi++; accR += s_b[hi]; }
                    int lob = w0 + lo, hib = w0 + hi;
                    if (lob == 0x8000) lob--;
                    if (hib == 0x7fff) hib++;
                    if (lob < 0) lob = 0;
                    if (hib > 65535) hib = 65535;
                    unsigned klo = (unsigned)lob << 16;
                    unsigned khi = ((unsigned)hib << 16) | 0xffffu;
                    unsigned range = khi - klo, sh = 0u;
                    while ((range >> sh) >= 2048u) sh++;
                    s_klo = klo; s_shift = sh;
                    s_flo = key2f(klo); s_fhi = key2f(khi);
                    s_pickok = 1u;
                }
            }
        }
        __syncthreads();
        if (!s_pickok && tid == 0) { s_flo = 1.0f; s_fhi = 0.0f; s_klo = 0u; s_shift = 0u; }
        __syncthreads();
    }

    // ---- Phase C2: main fused pass (4x batched loads for MLP) ----
    const float flo = s_flo, fhi = s_fhi;
    const unsigned klo = s_klo, sh = s_shift;
    const unsigned pickok = s_pickok;
    __syncthreads();   // C1's s_b window walk done before s_b reuse below
    {
        for (int i = tid; i < 2048; i += BLOCK) s_h[i] = 0u;
        if (tid == 0) { s_cnt = 0u; s_below = 0u; }
        __syncthreads();
        unsigned below = 0u;
        float4* o4 = (float4*)out;
        int i = bid * BLOCK + tid;
        for (; i + 3 * gstride < n4; i += 4 * gstride) {
            float4 v0 = __ldcs(&x4[i]);
            float4 v1 = __ldcs(&x4[i + gstride]);
            float4 v2 = __ldcs(&x4[i + 2 * gstride]);
            float4 v3 = __ldcs(&x4[i + 3 * gstride]);
            float4 r0, r1, r2, r3;
            r0.x = (v0.x > fhi) ? 1.0f : 0.0f; r0.y = (v0.y > fhi) ? 1.0f : 0.0f;
            r0.z = (v0.z > fhi) ? 1.0f : 0.0f; r0.w = (v0.w > fhi) ? 1.0f : 0.0f;
            r1.x = (v1.x > fhi) ? 1.0f : 0.0f; r1.y = (v1.y > fhi) ? 1.0f : 0.0f;
            r1.z = (v1.z > fhi) ? 1.0f : 0.0f; r1.w = (v1.w > fhi) ? 1.0f : 0.0f;
            r2.x = (v2.x > fhi) ? 1.0f : 0.0f; r2.y = (v2.y > fhi) ? 1.0f : 0.0f;
            r2.z = (v2.z > fhi) ? 1.0f : 0.0f; r2.w = (v2.w > fhi) ? 1.0f : 0.0f;
            r3.x = (v3.x > fhi) ? 1.0f : 0.0f; r3.y = (v3.y > fhi) ? 1.0f : 0.0f;
            r3.z = (v3.z > fhi) ? 1.0f : 0.0f; r3.w = (v3.w > fhi) ? 1.0f : 0.0f;
            __stcs(&o4[i], r0);
            __stcs(&o4[i + gstride], r1);
            __stcs(&o4[i + 2 * gstride], r2);
            __stcs(&o4[i + 3 * gstride], r3);
            below += (v0.x < flo) + (v0.y < flo) + (v0.z < flo) + (v0.w < flo);
            below += (v1.x < flo) + (v1.y < flo) + (v1.z < flo) + (v1.w < flo);
            below += (v2.x < flo) + (v2.y < flo) + (v2.z < flo) + (v2.w < flo);
            below += (v3.x < flo) + (v3.y < flo) + (v3.z < flo) + (v3.w < flo);
            bool c0 = (v0.x >= flo && v0.x <= fhi) || (v0.y >= flo && v0.y <= fhi) ||
                      (v0.z >= flo && v0.z <= fhi) || (v0.w >= flo && v0.w <= fhi);
            bool c1 = (v1.x >= flo && v1.x <= fhi) || (v1.y >= flo && v1.y <= fhi) ||
                      (v1.z >= flo && v1.z <= fhi) || (v1.w >= flo && v1.w <= fhi);
            bool c2 = (v2.x >= flo && v2.x <= fhi) || (v2.y >= flo && v2.y <= fhi) ||
                      (v2.z >= flo && v2.z <= fhi) || (v2.w >= flo && v2.w <= fhi);
            bool c3 = (v3.x >= flo && v3.x <= fhi) || (v3.y >= flo && v3.y <= fhi) ||
                      (v3.z >= flo && v3.z <= fhi) || (v3.w >= flo && v3.w <= fhi);
            unsigned am = __activemask();
            if (__ballot_sync(am, c0 || c1 || c2 || c3)) {
#pragma unroll
                for (int u = 0; u < 4; u++) {
                    float4 v = (u == 0) ? v0 : (u == 1) ? v1 : (u == 2) ? v2 : v3;
                    unsigned e = (unsigned)(i + u * gstride) * 4u;
                    if (v.x >= flo && v.x <= fhi) {
                        unsigned key = f2key(v.x);
                        unsigned p = atomicAdd(&s_cnt, 1u);
                        if (p < STAGE_CAP) { s_a[p] = key; s_b[p] = e; atomicAdd(&s_h[min((key - klo) >> sh, 2047u)], 1u); }
                    }
                    if (v.y >= flo && v.y <= fhi) {
                        unsigned key = f2key(v.y);
                        unsigned p = atomicAdd(&s_cnt, 1u);
                        if (p < STAGE_CAP) { s_a[p] = key; s_b[p] = e + 1u; atomicAdd(&s_h[min((key - klo) >> sh, 2047u)], 1u); }
                    }
                    if (v.z >= flo && v.z <= fhi) {
                        unsigned key = f2key(v.z);
                        unsigned p = atomicAdd(&s_cnt, 1u);
                        if (p < STAGE_CAP) { s_a[p] = key; s_b[p] = e + 2u; atomicAdd(&s_h[min((key - klo) >> sh, 2047u)], 1u); }
                    }
                    if (v.w >= flo && v.w <= fhi) {
                        unsigned key = f2key(v.w);
                        unsigned p = atomicAdd(&s_cnt, 1u);
                        if (p < STAGE_CAP) { s_a[p] = key; s_b[p] = e + 3u; atomicAdd(&s_h[min((key - klo) >> sh, 2047u)], 1u); }
                    }
                }
            }
        }
        for (; i < n4; i += gstride) {
            float4 v = __ldcs(&x4[i]);
            float4 rr;
            rr.x = (v.x > fhi) ? 1.0f : 0.0f;
            rr.y = (v.y > fhi) ? 1.0f : 0.0f;
            rr.z = (v.z > fhi) ? 1.0f : 0.0f;
            rr.w = (v.w > fhi) ? 1.0f : 0.0f;
            __stcs(&o4[i], rr);
            below += (v.x < flo) + (v.y < flo) + (v.z < flo) + (v.w < flo);
            unsigned e = (unsigned)i * 4u;
            if (v.x >= flo && v.x <= fhi) {
                unsigned key = f2key(v.x);
                unsigned p = atomicAdd(&s_cnt, 1u);
                if (p < STAGE_CAP) { s_a[p] = key; s_b[p] = e; atomicAdd(&s_h[min((key - klo) >> sh, 2047u)], 1u); }
            }
            if (v.y >= flo && v.y <= fhi) {
                unsigned key = f2key(v.y);
                unsigned p = atomicAdd(&s_cnt, 1u);
                if (p < STAGE_CAP) { s_a[p] = key; s_b[p] = e + 1u; atomicAdd(&s_h[min((key - klo) >> sh, 2047u)], 1u); }
            }
            if (v.z >= flo && v.z <= fhi) {
                unsigned key = f2key(v.z);
                unsigned p = atomicAdd(&s_cnt, 1u);
                if (p < STAGE_CAP) { s_a[p] = key; s_b[p] = e + 2u; atomicAdd(&s_h[min((key - klo) >> sh, 2047u)], 1u); }
            }
            if (v.w >= flo && v.w <= fhi) {
                unsigned key = f2key(v.w);
                unsigned p = atomicAdd(&s_cnt, 1u);
                if (p < STAGE_CAP) { s_a[p] = key; s_b[p] = e + 3u; atomicAdd(&s_h[min((key - klo) >> sh, 2047u)], 1u); }
            }
        }
#pragma unroll
        for (int off = 16; off > 0; off >>= 1)
            below += __shfl_down_sync(0xffffffffu, below, off);
        if ((tid & 31) == 0) atomicAdd(&s_below, below);
        __syncthreads();
        unsigned cnt = s_cnt < STAGE_CAP ? s_cnt : STAGE_CAP;
        if (tid == 0) {
            if (s_cnt > STAGE_CAP) atomicExch(&g_overflow, 1u);
            atomicAdd(&g_below, s_below);
            s_base = atomicAdd(&g_count, cnt);
        }
        __syncthreads();
        unsigned base = s_base;
        for (unsigned j = tid; j < cnt; j += BLOCK) {
            g_cand[base + j] = s_a[j];
            g_cidx[base + j] = s_b[j];
        }
        for (int j = tid; j < 2048; j += BLOCK)
            if (s_h[j]) atomicAdd(&g_hist2048[j], s_h[j]);
        // scalar tail (n % 4), block 0 only
        if (bid == 0) {
            for (int j = (n & ~3) + tid; j < n; j += BLOCK) {
                float v = x[j];
                out[j] = (v > fhi) ? 1.0f : 0.0f;
                if (v < flo) atomicAdd(&g_below, 1u);
                else if (v >= flo && v <= fhi) {
                    unsigned key = f2key(v);
                    unsigned p = atomicAdd(&g_count, 1u);
                    if (p < CAND_CAP) {
                        g_cand[p] = key; g_cidx[p] = (unsigned)j;
                        atomicAdd(&g_hist2048[min((key - klo) >> sh, 2047u)], 1u);
                    } else atomicExch(&g_overflow, 1u);
                }
            }
        }
    }
    gsync(G);

    // ---- Phase D: level-1 select (local) + level-2 candidate hist ----
    unsigned nc, ok, b2base = 0u, rank2 = 0u, w = 1u;
    {
        for (int i = tid; i < 2048; i += BLOCK) s_h[i] = g_hist2048[i];
        unsigned below_g = g_below;
        nc = g_count;
        unsigned ovf = g_overflow;
        ok = pickok && (!ovf) && (idx >= below_g) && ((idx - below_g) < nc) && (nc <= CAND_CAP);
        if (tid == 0) s_obin = 0xffffffffu;
        __syncthreads();
        if (ok) {
            bsel(s_h, 2048, idx - below_g, &s_obin, &s_orank, s_wofs);
            if (s_obin == 0xffffffffu) ok = 0u;
            else {
                b2base = klo + (s_obin << sh);
                rank2 = s_orank;
                w = 1u << sh;
                for (int i = tid; i < 2048; i += BLOCK) s_a[i] = 0u;
                __syncthreads();
                for (unsigned i = bid * BLOCK + tid; i < nc; i += (unsigned)gstride) {
                    unsigned off = g_cand[i] - b2base;
                    if (off < w) atomicAdd(&s_a[min(off, 2047u)], 1u);
                }
                __syncthreads();
                unsigned wcap = w < 2048u ? w : 2048u;
                for (unsigned i = tid; i < wcap; i += BLOCK)
                    if (s_a[i]) atomicAdd(&g_hist2b[i], s_a[i]);
            }
        }
        // zero sample hist slice + partials (last read in phase C1)
        int base = bid * SLICE;
        for (int i = tid; i < SLICE; i += BLOCK) {
            int b = base + i;
            if (b < 65536) {
#pragma unroll
                for (int r = 0; r < REP; r++) g_shist[r * 65536 + b] = 0u;
            }
        }
        if (tid == 0) g_part[bid] = 0u;
    }
    gsync(G);

    // ---- Phase E: threshold select (local) + cleanup + fixup ----
    {
        for (int i = tid; i < 2048; i += BLOCK) s_h[i] = g_hist2b[i];
        if (tid == 0) s_obin = 0xffffffffu;
        __syncthreads();
        float thr = __int_as_float(0x7f800000);
        if (ok) {
            int nb = (int)(w < 2048u ? w : 2048u);
            bsel(s_h, nb, rank2, &s_obin, &s_orank, s_wofs);
            if (s_obin == 0xffffffffu) ok = 0u;
            else thr = key2f(b2base + s_obin);
        }
        gsync(G);
        // cleanup (everyone staged what they need)
        for (int i = bid * BLOCK + tid; i < 2048; i += gstride) {
            g_hist2048[i] = 0u;
            g_hist2b[i] = 0u;
        }
        if (bid == 0 && tid == 0) {
            g_below = 0u; g_count = 0u; g_overflow = 0u;
        }
        if (ok) {
            for (unsigned i = bid * BLOCK + tid; i < nc; i += (unsigned)gstride)
                if (key2f(g_cand[i]) >= thr) out[g_cidx[i]] = 1.0f;
        }
    }

    // ---- Fallback phases (grid-uniform: every block computed the same ok) ----
    if (!ok) {
        // F0: zero the 64K hist
        for (int i = bid * BLOCK + tid; i < 65536; i += gstride) g_hist64k[i] = 0u;
        gsync(G);
        // F1: exact full-data hist on high 16 key bits
        for (int i = bid * BLOCK + tid; i < n; i += gstride)
            atomicAdd(&g_hist64k[f2key(x[i]) >> 16], 1u);
        gsync(G);
        // F2: every block selects the same (high-bin, rank) locally
        unsigned fb = 0u, fr = 0u;
        {
            unsigned ob, orr;
            sel64k(g_hist64k, idx, &ob, &orr, s_h, s_a, s_wofs, &s_obin, &s_orank);
            fb = ob; fr = orr;
        }
        gsync(G);                 // all blocks done reading before re-zero
        // F3: zero hist again
        for (int i = bid * BLOCK + tid; i < 65536; i += gstride) g_hist64k[i] = 0u;
        gsync(G);
        // F4: hist of low 16 bits for keys in bin fb
        if (fb != 0xffffffffu) {
            for (int i = bid * BLOCK + tid; i < n; i += gstride) {
                unsigned key = f2key(x[i]);
                if ((key >> 16) == fb) atomicAdd(&g_hist64k[key & 0xffffu], 1u);
            }
        }
        gsync(G);
        // F5: select low bin -> exact threshold; F6: full mask rewrite
        float thr2 = __int_as_float(0x7f800000);
        if (fb != 0xffffffffu) {
            unsigned ob, orr;
            sel64k(g_hist64k, fr, &ob, &orr, s_h, s_a, s_wofs, &s_obin, &s_orank);
            if (ob != 0xffffffffu) thr2 = key2f((fb << 16) | ob);
        }
        for (int i = bid * BLOCK + tid; i < n; i += gstride)
            out[i] = (x[i] >= thr2) ? 1.0f : 0.0f;
    }
}

__global__ void k_fill0(float* __restrict__ out, int n) {
    const int stride = gridDim.x * blockDim.x;
    for (int i = blockIdx.x * blockDim.x + threadIdx.x; i < n; i += stride)
        out[i] = 0.0f;
}

extern "C" void kernel_launch(void* const* d_in, const int* in_sizes, int n_in,
                              void* d_out, int out_size) {
    const float* x = (const float*)d_in[0];
    float* out = (float*)d_out;
    const long long n = (long long)in_sizes[0];
    const long long k = (long long)((double)n * 0.9);
    if (k <= 0) { k_fill0<<<1184, 256>>>(out, (int)n); return; }
    const unsigned idx = (unsigned)(n - k);   // 0-indexed ascending rank
    const int n4 = (int)(n >> 2);
    // sampled count: first 32 float4s of each 1024-float4 chunk
    const long long full = n4 / 1024, rem = n4 % 1024;
    const long long m4 = full * 32 + (rem < 32 ? rem : 32);
    const long long m = m4 * 4;
    unsigned t_target = 0u;
    if (m > 0) {
        t_target = (unsigned)((double)idx * (double)m / (double)n);
        if (t_target >= (unsigned)m) t_target = (unsigned)m - 1u;
    }

    int sm = 148, occ = 6, dev = 0;
    cudaGetDevice(&dev);
    cudaDeviceGetAttribute(&sm, cudaDevAttrMultiProcessorCount, dev);
    cudaOccupancyMaxActiveBlocksPerMultiprocessor(&occ, k_fused, BLOCK, 0);
    if (occ > 6) occ = 6;
    if (occ < 1) occ = 1;
    int G = sm * occ;
    if (G > MAXG) G = MAXG;
    if (G < 1) G = 1;

    k_fused<<<G, BLOCK>>>((const float4*)x, n4, x, (int)n, out, idx, t_target, G);
}

// round 13
// speedup vs baseline: 1.1516x; 1.0067x over previous
#include <cuda_runtime.h>

// Single persistent kernel: sampled radix-select threshold + fused mask,
// with the exact-radix fallback folded in as gated phases (single launch).
// Grid-wide sense barrier (co-residency guaranteed via occupancy API).
// Key map (order-preserving): neg -> ~bits, pos -> bits|0x80000000.

#define BLOCK     256
#define MAXG      2048
#define REP       8
#define STAGE_CAP 2048
#define CAND_CAP  (1u << 22)
#define MARGIN    3000u
#define MAX_EXP   15

static __device__ unsigned g_shist[REP * 65536];  // replicated sample hist
static __device__ unsigned g_part[MAXG];          // per-block slice partials
static __device__ unsigned g_hist2048[2048];      // level-1 candidate hist
static __device__ unsigned g_hist2b[2048];        // level-2 candidate hist
static __device__ unsigned g_hist64k[65536];      // fallback-only hist
static __device__ unsigned g_below, g_count, g_overflow;
static __device__ unsigned g_bar_count, g_bar_gen;
static __device__ unsigned g_cand[CAND_CAP];
static __device__ unsigned g_cidx[CAND_CAP];

__device__ __forceinline__ unsigned f2key(float f) {
    unsigned u = __float_as_uint(f);
    return (u & 0x80000000u) ? ~u : (u | 0x80000000u);
}
__device__ __forceinline__ float key2f(unsigned key) {
    unsigned u = (key & 0x80000000u) ? (key & 0x7fffffffu) : ~key;
    return __uint_as_float(u);
}

// Grid barrier: sync-then-elect arrive; release via gen bump; volatile spin.
__device__ __forceinline__ void gsync(int G) {
    __syncthreads();
    if (threadIdx.x == 0) {
        __threadfence();
        unsigned gen = *(volatile unsigned*)&g_bar_gen;
        if (atomicAdd(&g_bar_count, 1u) == (unsigned)G - 1u) {
            g_bar_count = 0u;
            __threadfence();
            atomicAdd(&g_bar_gen, 1u);
        } else {
            while (*(volatile unsigned*)&g_bar_gen == gen) __nanosleep(64);
        }
        __threadfence();
    }
    __syncthreads();
}

// Block-parallel rank-select over smem hist (nb <= 2048, blockDim 256).
// Caller inits *o_bin = ~0u (+sync) before; ends with syncthreads.
__device__ __forceinline__ void bsel(const unsigned* h, int nb, unsigned target,
                                     unsigned* o_bin, unsigned* o_rank,
                                     unsigned* s_wofs) {
    int tid = threadIdx.x, lane = tid & 31, wid = tid >> 5;
    int C = (nb + BLOCK - 1) / BLOCK;
    int base = tid * C;
    unsigned my = 0u;
    for (int j = 0; j < C; j++) { int b = base + j; if (b < nb) my += h[b]; }
    unsigned v = my;
#pragma unroll
    for (int off = 1; off < 32; off <<= 1) {
        unsigned t = __shfl_up_sync(0xffffffffu, v, off);
        if (lane >= off) v += t;
    }
    if (lane == 31) s_wofs[wid + 1] = v;
    if (tid == 0) s_wofs[0] = 0u;
    __syncthreads();
    if (tid == 0) for (int w = 1; w <= 8; w++) s_wofs[w] += s_wofs[w - 1];
    __syncthreads();
    unsigned excl = s_wofs[wid] + v - my;
    if (my && target >= excl && target < excl + my) {
        unsigned cum = excl;
        for (int j = 0; j < C; j++) {
            int b = base + j; if (b >= nb) break;
            unsigned c = h[b];
            if (target < cum + c) { *o_bin = (unsigned)b; *o_rank = target - cum; break; }
            cum += c;
        }
    }
    __syncthreads();
}

// Two-level block-local select over the 64K global hist (fallback path).
// Every block computes the same (bin, rank) deterministically.
__device__ __forceinline__ void sel64k(const unsigned* gh, unsigned target,
                                       unsigned* o_bin, unsigned* o_rank,
                                       unsigned* s_h, unsigned* s_a,
                                       unsigned* s_wofs,
                                       unsigned* s_obin, unsigned* s_orank) {
    int tid = threadIdx.x;
    for (int g = tid; g < 1024; g += BLOCK) {
        unsigned s = 0u;
        for (int j = 0; j < 64; j++) s += gh[g * 64 + j];
        s_h[g] = s;
    }
    if (tid == 0) *s_obin = 0xffffffffu;
    __syncthreads();
    bsel(s_h, 1024, target, s_obin, s_orank, s_wofs);
    unsigned grp = *s_obin, grank = *s_orank;
    *o_bin = 0xffffffffu;
    if (grp != 0xffffffffu) {
        for (int j = tid; j < 64; j += BLOCK) s_a[j] = gh[grp * 64 + j];
        if (tid == 0) *s_obin = 0xffffffffu;
        __syncthreads();
        bsel(s_a, 64, grank, s_obin, s_orank, s_wofs);
        if (*s_obin != 0xffffffffu) {
            *o_bin = grp * 64u + *s_obin;
            *o_rank = *s_orank;
        }
    }
    __syncthreads();
}

__global__ __launch_bounds__(BLOCK, 6)
void k_fused(const float4* __restrict__ x4, int n4,
             const float* __restrict__ x, int n,
             float* __restrict__ out, unsigned idx, unsigned t_target, int G) {
    __shared__ unsigned s_a[2048];       // pick: slice | main: cand keys | D: lvl2 hist
    __shared__ unsigned s_b[2048];       // pick: window | main: cand idx
    __shared__ unsigned s_h[2048];       // staging: partials/hists | main: lvl1 hist
    __shared__ unsigned s_wofs[9];
    __shared__ unsigned s_obin, s_orank, s_cnt, s_below, s_base;
    __shared__ unsigned s_klo, s_shift, s_pickok;
    __shared__ float    s_flo, s_fhi;
    const int tid = threadIdx.x;
    const int bid = blockIdx.x;
    const int gstride = G * BLOCK;

    // ---- Phase A: coalesced sampling (first 32 float4s of each 1024 chunk) ----
    {
        const unsigned rbase = (unsigned)(bid & (REP - 1)) * 65536u;
        const int nchunks = (n4 + 1023) / 1024;
        for (int t = bid * BLOCK + tid; t < nchunks * 32; t += gstride) {
            int i = (t >> 5) * 1024 + (t & 31);
            if (i < n4) {
                float4 v = __ldg(&x4[i]);
                atomicAdd(&g_shist[rbase + (f2key(v.x) >> 16)], 1u);
                atomicAdd(&g_shist[rbase + (f2key(v.y) >> 16)], 1u);
                atomicAdd(&g_shist[rbase + (f2key(v.z) >> 16)], 1u);
                atomicAdd(&g_shist[rbase + (f2key(v.w) >> 16)], 1u);
            }
        }
    }
    gsync(G);

    // ---- Phase B: per-block slice partial sums ----
    const int SLICE = (65536 + G - 1) / G;
    {
        int base = bid * SLICE;
        unsigned sum = 0u;
        for (int i = tid; i < SLICE; i += BLOCK) {
            int b = base + i;
            if (b < 65536) {
                unsigned s = 0u;
#pragma unroll
                for (int r = 0; r < REP; r++) s += g_shist[r * 65536 + b];
                sum += s;
            }
        }
#pragma unroll
        for (int off = 16; off > 0; off >>= 1)
            sum += __shfl_down_sync(0xffffffffu, sum, off);
        if ((tid & 31) == 0) s_wofs[tid >> 5] = sum;
        __syncthreads();
        if (tid == 0) {
            unsigned t = 0u;
            for (int w = 0; w < 8; w++) t += s_wofs[w];
            g_part[bid] = t;
        }
        __syncthreads();
    }
    gsync(G);

    // ---- Phase C1: every block computes the SAME pick locally ----
    {
        for (int i = tid; i < G; i += BLOCK) s_h[i] = g_part[i];
        if (tid == 0) { s_obin = 0xffffffffu; s_pickok = 0u; }
        __syncthreads();
        bsel(s_h, G, t_target, &s_obin, &s_orank, s_wofs);
        int seg = (int)s_obin;
        unsigned segrank = s_orank;
        if (seg != -1) {
            int base = seg * SLICE;
            int nb = 65536 - base; if (nb > SLICE) nb = SLICE;
            for (int i = tid; i < nb; i += BLOCK) {
                unsigned s = 0u;
#pragma unroll
                for (int r = 0; r < REP; r++) s += g_shist[r * 65536 + base + i];
                s_a[i] = s;
            }
            if (tid == 0) s_obin = 0xffffffffu;
            __syncthreads();
            bsel(s_a, nb, segrank, &s_obin, &s_orank, s_wofs);
            int bc = (s_obin == 0xffffffffu) ? -1 : base + (int)s_obin;
            if (bc >= 0) {
                int w0 = bc - 16;
                for (int i = tid; i < 33; i += BLOCK) {
                    int b = w0 + i;
                    unsigned s = 0u;
                    if (b >= 0 && b < 65536) {
#pragma unroll
                        for (int r = 0; r < REP; r++) s += g_shist[r * 65536 + b];
                    }
                    s_b[i] = s;
                }
                __syncthreads();
                if (tid == 0) {
                    int lo = 16; unsigned accL = 0u;
                    while ((w0 + lo) > 0 && accL < MARGIN && (16 - lo) < MAX_EXP) { lo--; accL += s_b[lo]; }
                    int hi = 16; unsigned accR = 0u;
                    while ((w0 + hi) < 65535 && accR < MARGIN && (hi - 16) < MAX_EXP) { hi++; accR += s_b[hi]; }
                    int lob = w0 + lo, hib = w0 + hi;
                    if (lob == 0x8000) lob--;
                    if (hib == 0x7fff) hib++;
                    if (lob < 0) lob = 0;
                    if (hib > 65535) hib = 65535;
                    unsigned klo = (unsigned)lob << 16;
                    unsigned khi = ((unsigned)hib << 16) | 0xffffu;
                    unsigned range = khi - klo, sh = 0u;
                    while ((range >> sh) >= 2048u) sh++;
                    s_klo = klo; s_shift = sh;
                    s_flo = key2f(klo); s_fhi = key2f(khi);
                    s_pickok = 1u;
                }
            }
        }
        __syncthreads();
        if (!s_pickok && tid == 0) { s_flo = 1.0f; s_fhi = 0.0f; s_klo = 0u; s_shift = 0u; }
        __syncthreads();
    }

    // ---- Phase C2: main fused pass (4x batched loads for MLP) ----
    const float flo = s_flo, fhi = s_fhi;
    const unsigned klo = s_klo, sh = s_shift;
    const unsigned pickok = s_pickok;
    __syncthreads();   // C1's s_b window walk done before s_b reuse below
    {
        for (int i = tid; i < 2048; i += BLOCK) s_h[i] = 0u;
        if (tid == 0) { s_cnt = 0u; s_below = 0u; }
        __syncthreads();
        unsigned below = 0u;
        float4* o4 = (float4*)out;
        int i = bid * BLOCK + tid;
        for (; i + 3 * gstride < n4; i += 4 * gstride) {
            float4 v0 = __ldcs(&x4[i]);
            float4 v1 = __ldcs(&x4[i + gstride]);
            float4 v2 = __ldcs(&x4[i + 2 * gstride]);
            float4 v3 = __ldcs(&x4[i + 3 * gstride]);
            float4 r0, r1, r2, r3;
            r0.x = (v0.x > fhi) ? 1.0f : 0.0f; r0.y = (v0.y > fhi) ? 1.0f : 0.0f;
            r0.z = (v0.z > fhi) ? 1.0f : 0.0f; r0.w = (v0.w > fhi) ? 1.0f : 0.0f;
            r1.x = (v1.x > fhi) ? 1.0f : 0.0f; r1.y = (v1.y > fhi) ? 1.0f : 0.0f;
            r1.z = (v1.z > fhi) ? 1.0f : 0.0f; r1.w = (v1.w > fhi) ? 1.0f : 0.0f;
            r2.x = (v2.x > fhi) ? 1.0f : 0.0f; r2.y = (v2.y > fhi) ? 1.0f : 0.0f;
            r2.z = (v2.z > fhi) ? 1.0f : 0.0f; r2.w = (v2.w > fhi) ? 1.0f : 0.0f;
            r3.x = (v3.x > fhi) ? 1.0f : 0.0f; r3.y = (v3.y > fhi) ? 1.0f : 0.0f;
            r3.z = (v3.z > fhi) ? 1.0f : 0.0f; r3.w = (v3.w > fhi) ? 1.0f : 0.0f;
            __stcs(&o4[i], r0);
            __stcs(&o4[i + gstride], r1);
            __stcs(&o4[i + 2 * gstride], r2);
            __stcs(&o4[i + 3 * gstride], r3);
            below += (v0.x < flo) + (v0.y < flo) + (v0.z < flo) + (v0.w < flo);
            below += (v1.x < flo) + (v1.y < flo) + (v1.z < flo) + (v1.w < flo);
            below += (v2.x < flo) + (v2.y < flo) + (v2.z < flo) + (v2.w < flo);
            below += (v3.x < flo) + (v3.y < flo) + (v3.z < flo) + (v3.w < flo);
            bool c0 = (v0.x >= flo && v0.x <= fhi) || (v0.y >= flo && v0.y <= fhi) ||
                      (v0.z >= flo && v0.z <= fhi) || (v0.w >= flo && v0.w <= fhi);
            bool c1 = (v1.x >= flo && v1.x <= fhi) || (v1.y >= flo && v1.y <= fhi) ||
                      (v1.z >= flo && v1.z <= fhi) || (v1.w >= flo && v1.w <= fhi);
            bool c2 = (v2.x >= flo && v2.x <= fhi) || (v2.y >= flo && v2.y <= fhi) ||
                      (v2.z >= flo && v2.z <= fhi) || (v2.w >= flo && v2.w <= fhi);
            bool c3 = (v3.x >= flo && v3.x <= fhi) || (v3.y >= flo && v3.y <= fhi) ||
                      (v3.z >= flo && v3.z <= fhi) || (v3.w >= flo && v3.w <= fhi);
            unsigned am = __activemask();
            if (__ballot_sync(am, c0 || c1 || c2 || c3)) {
#pragma unroll
                for (int u = 0; u < 4; u++) {
                    float4 v = (u == 0) ? v0 : (u == 1) ? v1 : (u == 2) ? v2 : v3;
                    unsigned e = (unsigned)(i + u * gstride) * 4u;
                    if (v.x >= flo && v.x <= fhi) {
                        unsigned key = f2key(v.x);
                        unsigned p = atomicAdd(&s_cnt, 1u);
                        if (p < STAGE_CAP) { s_a[p] = key; s_b[p] = e; atomicAdd(&s_h[min((key - klo) >> sh, 2047u)], 1u); }
                    }
                    if (v.y >= flo && v.y <= fhi) {
                        unsigned key = f2key(v.y);
                        unsigned p = atomicAdd(&s_cnt, 1u);
                        if (p < STAGE_CAP) { s_a[p] = key; s_b[p] = e + 1u; atomicAdd(&s_h[min((key - klo) >> sh, 2047u)], 1u); }
                    }
                    if (v.z >= flo && v.z <= fhi) {
                        unsigned key = f2key(v.z);
                        unsigned p = atomicAdd(&s_cnt, 1u);
                        if (p < STAGE_CAP) { s_a[p] = key; s_b[p] = e + 2u; atomicAdd(&s_h[min((key - klo) >> sh, 2047u)], 1u); }
                    }
                    if (v.w >= flo && v.w <= fhi) {
                        unsigned key = f2key(v.w);
                        unsigned p = atomicAdd(&s_cnt, 1u);
                        if (p < STAGE_CAP) { s_a[p] = key; s_b[p] = e + 3u; atomicAdd(&s_h[min((key - klo) >> sh, 2047u)], 1u); }
                    }
                }
            }
        }
        for (; i < n4; i += gstride) {
            float4 v = __ldcs(&x4[i]);
            float4 rr;
            rr.x = (v.x > fhi) ? 1.0f : 0.0f;
            rr.y = (v.y > fhi) ? 1.0f : 0.0f;
            rr.z = (v.z > fhi) ? 1.0f : 0.0f;
            rr.w = (v.w > fhi) ? 1.0f : 0.0f;
            __stcs(&o4[i], rr);
            below += (v.x < flo) + (v.y < flo) + (v.z < flo) + (v.w < flo);
            unsigned e = (unsigned)i * 4u;
            if (v.x >= flo && v.x <= fhi) {
                unsigned key = f2key(v.x);
                unsigned p = atomicAdd(&s_cnt, 1u);
                if (p < STAGE_CAP) { s_a[p] = key; s_b[p] = e; atomicAdd(&s_h[min((key - klo) >> sh, 2047u)], 1u); }
            }
            if (v.y >= flo && v.y <= fhi) {
                unsigned key = f2key(v.y);
                unsigned p = atomicAdd(&s_cnt, 1u);
                if (p < STAGE_CAP) { s_a[p] = key; s_b[p] = e + 1u; atomicAdd(&s_h[min((key - klo) >> sh, 2047u)], 1u); }
            }
            if (v.z >= flo && v.z <= fhi) {
                unsigned key = f2key(v.z);
                unsigned p = atomicAdd(&s_cnt, 1u);
                if (p < STAGE_CAP) { s_a[p] = key; s_b[p] = e + 2u; atomicAdd(&s_h[min((key - klo) >> sh, 2047u)], 1u); }
            }
            if (v.w >= flo && v.w <= fhi) {
                unsigned key = f2key(v.w);
                unsigned p = atomicAdd(&s_cnt, 1u);
                if (p < STAGE_CAP) { s_a[p] = key; s_b[p] = e + 3u; atomicAdd(&s_h[min((key - klo) >> sh, 2047u)], 1u); }
            }
        }
#pragma unroll
        for (int off = 16; off > 0; off >>= 1)
            below += __shfl_down_sync(0xffffffffu, below, off);
        if ((tid & 31) == 0) atomicAdd(&s_below, below);
        __syncthreads();
        unsigned cnt = s_cnt < STAGE_CAP ? s_cnt : STAGE_CAP;
        if (tid == 0) {
            if (s_cnt > STAGE_CAP) atomicExch(&g_overflow, 1u);
            atomicAdd(&g_below, s_below);
            s_base = atomicAdd(&g_count, cnt);
        }
        __syncthreads();
        unsigned base = s_base;
        for (unsigned j = tid; j < cnt; j += BLOCK) {
            g_cand[base + j] = s_a[j];
            g_cidx[base + j] = s_b[j];
        }
        for (int j = tid; j < 2048; j += BLOCK)
            if (s_h[j]) atomicAdd(&g_hist2048[j], s_h[j]);
        // scalar tail (n % 4), block 0 only
        if (bid == 0) {
            for (int j = (n & ~3) + tid; j < n; j += BLOCK) {
                float v = x[j];
                out[j] = (v > fhi) ? 1.0f : 0.0f;
                if (v < flo) atomicAdd(&g_below, 1u);
                else if (v >= flo && v <= fhi) {
                    unsigned key = f2key(v);
                    unsigned p = atomicAdd(&g_count, 1u);
                    if (p < CAND_CAP) {
                        g_cand[p] = key; g_cidx[p] = (unsigned)j;
                        atomicAdd(&g_hist2048[min((key - klo) >> sh, 2047u)], 1u);
                    } else atomicExch(&g_overflow, 1u);
                }
            }
        }
    }
    gsync(G);

    // ---- Phase D: level-1 select (local) + level-2 candidate hist ----
    unsigned nc, ok, b2base = 0u, rank2 = 0u, w = 1u;
    {
        for (int i = tid; i < 2048; i += BLOCK) s_h[i] = g_hist2048[i];
        unsigned below_g = g_below;
        nc = g_count;
        unsigned ovf = g_overflow;
        ok = pickok && (!ovf) && (idx >= below_g) && ((idx - below_g) < nc) && (nc <= CAND_CAP);
        if (tid == 0) s_obin = 0xffffffffu;
        __syncthreads();
        if (ok) {
            bsel(s_h, 2048, idx - below_g, &s_obin, &s_orank, s_wofs);
            if (s_obin == 0xffffffffu) ok = 0u;
            else {
                b2base = klo + (s_obin << sh);
                rank2 = s_orank;
                w = 1u << sh;
                for (int i = tid; i < 2048; i += BLOCK) s_a[i] = 0u;
                __syncthreads();
                for (unsigned i = bid * BLOCK + tid; i < nc; i += (unsigned)gstride) {
                    unsigned off = g_cand[i] - b2base;
                    if (off < w) atomicAdd(&s_a[min(off, 2047u)], 1u);
                }
                __syncthreads();
                unsigned wcap = w < 2048u ? w : 2048u;
                for (unsigned i = tid; i < wcap; i += BLOCK)
                    if (s_a[i]) atomicAdd(&g_hist2b[i], s_a[i]);
            }
        }
        // zero sample hist slice + partials (last read in phase C1)
        int base = bid * SLICE;
        for (int i = tid; i < SLICE; i += BLOCK) {
            int b = base + i;
            if (b < 65536) {
#pragma unroll
                for (int r = 0; r < REP; r++) g_shist[r * 65536 + b] = 0u;
            }
        }
        if (tid == 0) g_part[bid] = 0u;
    }
    gsync(G);

    // ---- Phase E: threshold select (local) + cleanup + fixup ----
    {
        for (int i = tid; i < 2048; i += BLOCK) s_h[i] = g_hist2b[i];
        if (tid == 0) s_obin = 0xffffffffu;
        __syncthreads();
        float thr = __int_as_float(0x7f800000);
        if (ok) {
            int nb = (int)(w < 2048u ? w : 2048u);
            bsel(s_h, nb, rank2, &s_obin, &s_orank, s_wofs);
            if (s_obin == 0xffffffffu) ok = 0u;
            else thr = key2f(b2base + s_obin);
        }
        gsync(G);
        // cleanup (everyone staged what they need)
        for (int i = bid * BLOCK + tid; i < 2048; i += gstride) {
            g_hist2048[i] = 0u;
            g_hist2b[i] = 0u;
        }
        if (bid == 0 && tid == 0) {
            g_below = 0u; g_count = 0u; g_overflow = 0u;
        }
        if (ok) {
            for (unsigned i = bid * BLOCK + tid; i < nc; i += (unsigned)gstride)
                if (key2f(g_cand[i]) >= thr) out[g_cidx[i]] = 1.0f;
        }
    }

    // ---- Fallback phases (grid-uniform: every block computed the same ok) ----
    if (!ok) {
        // F0: zero the 64K hist
        for (int i = bid * BLOCK + tid; i < 65536; i += gstride) g_hist64k[i] = 0u;
        gsync(G);
        // F1: exact full-data hist on high 16 key bits
        for (int i = bid * BLOCK + tid; i < n; i += gstride)
            atomicAdd(&g_hist64k[f2key(x[i]) >> 16], 1u);
        gsync(G);
        // F2: every block selects the same (high-bin, rank) locally
        unsigned fb = 0u, fr = 0u;
        {
            unsigned ob, orr;
            sel64k(g_hist64k, idx, &ob, &orr, s_h, s_a, s_wofs, &s_obin, &s_orank);
            fb = ob; fr = orr;
        }
        gsync(G);                 // all blocks done reading before re-zero
        // F3: zero hist again
        for (int i = bid * BLOCK + tid; i < 65536; i += gstride) g_hist64k[i] = 0u;
        gsync(G);
        // F4: hist of low 16 bits for keys in bin fb
        if (fb != 0xffffffffu) {
            for (int i = bid * BLOCK + tid; i < n; i += gstride) {
                unsigned key = f2key(x[i]);
                if ((key >> 16) == fb) atomicAdd(&g_hist64k[key & 0xffffu], 1u);
            }
        }
        gsync(G);
        // F5: select low bin -> exact threshold; F6: full mask rewrite
        float thr2 = __int_as_float(0x7f800000);
        if (fb != 0xffffffffu) {
            unsigned ob, orr;
            sel64k(g_hist64k, fr, &ob, &orr, s_h, s_a, s_wofs, &s_obin, &s_orank);
            if (ob != 0xffffffffu) thr2 = key2f((fb << 16) | ob);
        }
        for (int i = bid * BLOCK + tid; i < n; i += gstride)
            out[i] = (x[i] >= thr2) ? 1.0f : 0.0f;
    }
}

__global__ void k_fill0(float* __restrict__ out, int n) {
    const int stride = gridDim.x * blockDim.x;
    for (int i = blockIdx.x * blockDim.x + threadIdx.x; i < n; i += stride)
        out[i] = 0.0f;
}

extern "C" void kernel_launch(void* const* d_in, const int* in_sizes, int n_in,
                              void* d_out, int out_size) {
    const float* x = (const float*)d_in[0];
    float* out = (float*)d_out;
    const long long n = (long long)in_sizes[0];
    const long long k = (long long)((double)n * 0.9);
    if (k <= 0) { k_fill0<<<1184, 256>>>(out, (int)n); return; }
    const unsigned idx = (unsigned)(n - k);   // 0-indexed ascending rank
    const int n4 = (int)(n >> 2);
    // sampled count: first 32 float4s of each 1024-float4 chunk
    const long long full = n4 / 1024, rem = n4 % 1024;
    const long long m4 = full * 32 + (rem < 32 ? rem : 32);
    const long long m = m4 * 4;
    unsigned t_target = 0u;
    if (m > 0) {
        t_target = (unsigned)((double)idx * (double)m / (double)n);
        if (t_target >= (unsigned)m) t_target = (unsigned)m - 1u;
    }

    int sm = 148, occ = 6, dev = 0;
    cudaGetDevice(&dev);
    cudaDeviceGetAttribute(&sm, cudaDevAttrMultiProcessorCount, dev);
    cudaOccupancyMaxActiveBlocksPerMultiprocessor(&occ, k_fused, BLOCK, 0);
    if (occ > 6) occ = 6;
    if (occ < 1) occ = 1;
    int G = sm * occ;
    if (G > MAXG) G = MAXG;
    if (G < 1) G = 1;

    k_fused<<<G, BLOCK>>>((const float4*)x, n4, x, (int)n, out, idx, t_target, G);
}

// round 14
// speedup vs baseline: 1.5216x; 1.3213x over previous
#include <cuda_runtime.h>

// Single persistent kernel: two-level sampled radix-select threshold + fused
// mask, exact-radix fallback folded in as gated phases (single launch).
// Grid-wide sense barrier (co-residency guaranteed via occupancy API).
// Key map (order-preserving): neg -> ~bits, pos -> bits|0x80000000.

#define BLOCK     256
#define MAXG      2048
#define STAGE_CAP 2048
#define CAND_CAP  (1u << 22)
#define MARGIN    3500u
#define EXP_CAP   256
#define A2BLOCKS  128

static __device__ unsigned g_coarse[256];     // sample hist, high 8 key bits
static __device__ unsigned g_fine[2048];      // sample hist, 2-segment window
static __device__ unsigned g_hist2048[2048];  // level-1 candidate hist
static __device__ unsigned g_hist2b[2048];    // level-2 candidate hist
static __device__ unsigned g_hist64k[65536];  // fallback-only hist
static __device__ unsigned g_below, g_count, g_overflow;
static __device__ unsigned g_bar_count, g_bar_gen;
static __device__ unsigned g_cand[CAND_CAP];
static __device__ unsigned g_cidx[CAND_CAP];

__device__ __forceinline__ unsigned f2key(float f) {
    unsigned u = __float_as_uint(f);
    return (u & 0x80000000u) ? ~u : (u | 0x80000000u);
}
__device__ __forceinline__ float key2f(unsigned key) {
    unsigned u = (key & 0x80000000u) ? (key & 0x7fffffffu) : ~key;
    return __uint_as_float(u);
}

// Grid barrier: sync-then-elect arrive; release via gen bump; volatile spin.
__device__ __forceinline__ void gsync(int G) {
    __syncthreads();
    if (threadIdx.x == 0) {
        __threadfence();
        unsigned gen = *(volatile unsigned*)&g_bar_gen;
        if (atomicAdd(&g_bar_count, 1u) == (unsigned)G - 1u) {
            g_bar_count = 0u;
            __threadfence();
            atomicAdd(&g_bar_gen, 1u);
        } else {
            while (*(volatile unsigned*)&g_bar_gen == gen) __nanosleep(64);
        }
        __threadfence();
    }
    __syncthreads();
}

// Block-parallel rank-select over smem hist (nb <= 2048, blockDim 256).
__device__ __forceinline__ void bsel(const unsigned* h, int nb, unsigned target,
                                     unsigned* o_bin, unsigned* o_rank,
                                     unsigned* s_wofs) {
    int tid = threadIdx.x, lane = tid & 31, wid = tid >> 5;
    int C = (nb + BLOCK - 1) / BLOCK;
    int base = tid * C;
    unsigned my = 0u;
    for (int j = 0; j < C; j++) { int b = base + j; if (b < nb) my += h[b]; }
    unsigned v = my;
#pragma unroll
    for (int off = 1; off < 32; off <<= 1) {
        unsigned t = __shfl_up_sync(0xffffffffu, v, off);
        if (lane >= off) v += t;
    }
    if (lane == 31) s_wofs[wid + 1] = v;
    if (tid == 0) s_wofs[0] = 0u;
    __syncthreads();
    if (tid == 0) for (int w = 1; w <= 8; w++) s_wofs[w] += s_wofs[w - 1];
    __syncthreads();
    unsigned excl = s_wofs[wid] + v - my;
    if (my && target >= excl && target < excl + my) {
        unsigned cum = excl;
        for (int j = 0; j < C; j++) {
            int b = base + j; if (b >= nb) break;
            unsigned c = h[b];
            if (target < cum + c) { *o_bin = (unsigned)b; *o_rank = target - cum; break; }
            cum += c;
        }
    }
    __syncthreads();
}

// Deterministic 2-segment window pick from staged coarse hist (s_c[256]).
// Returns wseg (or ~0u) and the exact sample count below the window.
__device__ __forceinline__ unsigned window_pick(unsigned t_target, const unsigned* s_c,
                                                unsigned* s_wofs, unsigned* s_obin,
                                                unsigned* s_orank, unsigned* o_below_w) {
    if (threadIdx.x == 0) *s_obin = 0xffffffffu;
    __syncthreads();
    bsel(s_c, 256, t_target, s_obin, s_orank, s_wofs);
    unsigned seg = *s_obin, rank = *s_orank;
    if (seg == 0xffffffffu) return 0xffffffffu;
    unsigned cnt = s_c[seg];
    unsigned wseg = seg;
    if (rank * 2 < cnt && seg > 0) wseg = seg - 1;
    if (wseg > 254u) wseg = 254u;
    unsigned excl = t_target - rank;            // samples in segments < seg
    *o_below_w = excl - ((wseg < seg) ? s_c[wseg] : 0u);
    return wseg;
}

// Two-level block-local select over 64K global hist (fallback path).
__device__ __forceinline__ void sel64k(const unsigned* gh, unsigned target,
                                       unsigned* o_bin, unsigned* o_rank,
                                       unsigned* s_h, unsigned* s_a,
                                       unsigned* s_wofs,
                                       unsigned* s_obin, unsigned* s_orank) {
    int tid = threadIdx.x;
    for (int g = tid; g < 1024; g += BLOCK) {
        unsigned s = 0u;
        for (int j = 0; j < 64; j++) s += gh[g * 64 + j];
        s_h[g] = s;
    }
    if (tid == 0) *s_obin = 0xffffffffu;
    __syncthreads();
    bsel(s_h, 1024, target, s_obin, s_orank, s_wofs);
    unsigned grp = *s_obin, grank = *s_orank;
    *o_bin = 0xffffffffu;
    if (grp != 0xffffffffu) {
        for (int j = tid; j < 64; j += BLOCK) s_a[j] = gh[grp * 64 + j];
        if (tid == 0) *s_obin = 0xffffffffu;
        __syncthreads();
        bsel(s_a, 64, grank, s_obin, s_orank, s_wofs);
        if (*s_obin != 0xffffffffu) {
            *o_bin = grp * 64u + *s_obin;
            *o_rank = *s_orank;
        }
    }
    __syncthreads();
}

__global__ __launch_bounds__(BLOCK, 6)
void k_fused(const float4* __restrict__ x4, int n4,
             const float* __restrict__ x, int n,
             float* __restrict__ out, unsigned idx, unsigned t_target, int G) {
    __shared__ unsigned s_a[2048];
    __shared__ unsigned s_b[2048];
    __shared__ unsigned s_h[2048];
    __shared__ unsigned s_wofs[9];
    __shared__ unsigned s_obin, s_orank, s_cnt, s_below, s_base;
    __shared__ unsigned s_klo, s_shift, s_pickok;
    __shared__ float    s_flo, s_fhi;
    const int tid = threadIdx.x;
    const int bid = blockIdx.x;
    const int gstride = G * BLOCK;
    const int nchunks = (n4 + 1023) / 1024;
    const int nsamp4 = nchunks * 64;            // sampled float4 slots

    // ---- Phase A: coarse smem hist (8 replicas) of 1/16 subsample ----
    {
        for (int i = tid; i < 2048; i += BLOCK) s_h[i] = 0u;
        __syncthreads();
        unsigned rep = ((unsigned)(tid >> 5) & 7u) * 256u;
        for (int t = bid * BLOCK + tid; t < nsamp4; t += gstride) {
            int i = (t >> 6) * 1024 + (t & 63);
            if (i < n4) {
                float4 v = __ldg(&x4[i]);
                atomicAdd(&s_h[rep + (f2key(v.x) >> 24)], 1u);
                atomicAdd(&s_h[rep + (f2key(v.y) >> 24)], 1u);
                atomicAdd(&s_h[rep + (f2key(v.z) >> 24)], 1u);
                atomicAdd(&s_h[rep + (f2key(v.w) >> 24)], 1u);
            }
        }
        __syncthreads();
        if (tid < 256) {
            unsigned c = 0u;
#pragma unroll
            for (int r = 0; r < 8; r++) c += s_h[r * 256 + tid];
            if (c) atomicAdd(&g_coarse[tid], c);
        }
    }
    gsync(G);

    // ---- Phase A2 (128 blocks): fine smem hist over the 2-segment window ----
    if (bid < A2BLOCKS) {
        for (int i = tid; i < 2048; i += BLOCK) { s_h[i] = 0u; s_a[i] = 0u; }
        if (tid < 256) s_b[tid] = g_coarse[tid];
        __syncthreads();
        unsigned below_w;
        unsigned wseg = window_pick(t_target, s_b, s_wofs, &s_obin, &s_orank, &below_w);
        if (wseg != 0xffffffffu) {
            const unsigned wlo = wseg << 24;
            unsigned* rep = (tid & 1) ? s_a : s_h;
            for (int t = bid * BLOCK + tid; t < nsamp4; t += A2BLOCKS * BLOCK) {
                int i = (t >> 6) * 1024 + (t & 63);
                if (i < n4) {
                    float4 v = __ldg(&x4[i]);
                    unsigned k0 = f2key(v.x) - wlo, k1 = f2key(v.y) - wlo;
                    unsigned k2 = f2key(v.z) - wlo, k3 = f2key(v.w) - wlo;
                    if (k0 < (1u << 25)) atomicAdd(&rep[k0 >> 14], 1u);
                    if (k1 < (1u << 25)) atomicAdd(&rep[k1 >> 14], 1u);
                    if (k2 < (1u << 25)) atomicAdd(&rep[k2 >> 14], 1u);
                    if (k3 < (1u << 25)) atomicAdd(&rep[k3 >> 14], 1u);
                }
            }
            __syncthreads();
            for (int i = tid; i < 2048; i += BLOCK) {
                unsigned c = s_h[i] + s_a[i];
                if (c) atomicAdd(&g_fine[i], c);
            }
        }
    }
    gsync(G);

    // ---- Phase C1: every block computes the SAME interval pick locally ----
    {
        if (tid < 256) s_b[tid] = g_coarse[tid];
        if (tid == 0) s_pickok = 0u;
        __syncthreads();
        unsigned below_w;
        unsigned wseg = window_pick(t_target, s_b, s_wofs, &s_obin, &s_orank, &below_w);
        for (int i = tid; i < 2048; i += BLOCK) s_h[i] = g_fine[i];
        if (tid == 0) s_obin = 0xffffffffu;
        __syncthreads();
        if (wseg != 0xffffffffu && t_target >= below_w) {
            bsel(s_h, 2048, t_target - below_w, &s_obin, &s_orank, s_wofs);
            if (tid == 0 && s_obin != 0xffffffffu) {
                const unsigned wlo = wseg << 24;
                int cb = (int)s_obin;
                int lo = cb; unsigned accL = 0u;
                while (lo > 0 && accL < MARGIN && (cb - lo) < EXP_CAP) { lo--; accL += s_h[lo]; }
                int hi = cb; unsigned accR = 0u;
                while (hi < 2047 && accR < MARGIN && (hi - cb) < EXP_CAP) { hi++; accR += s_h[hi]; }
                unsigned klo = wlo + ((unsigned)lo << 14);
                unsigned khi = wlo + ((unsigned)hi << 14) + 16383u;
                // keep the {-0,+0} pair entirely inside the interval
                if (klo == 0x80000000u) klo = 0x7fffffffu;
                if (khi == 0x7fffffffu) khi = 0x80000000u;
                unsigned range = khi - klo, sh = 0u;
                while ((range >> sh) >= 2048u) sh++;
                s_klo = klo; s_shift = sh;
                s_flo = key2f(klo); s_fhi = key2f(khi);
                s_pickok = 1u;
            }
        }
        __syncthreads();
        if (!s_pickok && tid == 0) { s_flo = 1.0f; s_fhi = 0.0f; s_klo = 0u; s_shift = 0u; }
        __syncthreads();
    }

    // ---- Phase C2: main fused pass (4x batched, 2 cmps/element) ----
    const float flo = s_flo, fhi = s_fhi;
    const unsigned klo = s_klo, sh = s_shift;
    const unsigned pickok = s_pickok;
    __syncthreads();
    {
        for (int i = tid; i < 2048; i += BLOCK) s_h[i] = 0u;
        if (tid == 0) { s_cnt = 0u; s_below = 0u; }
        __syncthreads();
        unsigned below = 0u;
        float4* o4 = (float4*)out;
        int i = bid * BLOCK + tid;
        for (; i + 3 * gstride < n4; i += 4 * gstride) {
            float4 v0 = __ldcs(&x4[i]);
            float4 v1 = __ldcs(&x4[i + gstride]);
            float4 v2 = __ldcs(&x4[i + 2 * gstride]);
            float4 v3 = __ldcs(&x4[i + 3 * gstride]);
            bool a00 = v0.x > fhi, a01 = v0.y > fhi, a02 = v0.z > fhi, a03 = v0.w > fhi;
            bool a10 = v1.x > fhi, a11 = v1.y > fhi, a12 = v1.z > fhi, a13 = v1.w > fhi;
            bool a20 = v2.x > fhi, a21 = v2.y > fhi, a22 = v2.z > fhi, a23 = v2.w > fhi;
            bool a30 = v3.x > fhi, a31 = v3.y > fhi, a32 = v3.z > fhi, a33 = v3.w > fhi;
            bool b00 = v0.x < flo, b01 = v0.y < flo, b02 = v0.z < flo, b03 = v0.w < flo;
            bool b10 = v1.x < flo, b11 = v1.y < flo, b12 = v1.z < flo, b13 = v1.w < flo;
            bool b20 = v2.x < flo, b21 = v2.y < flo, b22 = v2.z < flo, b23 = v2.w < flo;
            bool b30 = v3.x < flo, b31 = v3.y < flo, b32 = v3.z < flo, b33 = v3.w < flo;
            float4 r0, r1, r2, r3;
            r0.x = a00 ? 1.0f : 0.0f; r0.y = a01 ? 1.0f : 0.0f; r0.z = a02 ? 1.0f : 0.0f; r0.w = a03 ? 1.0f : 0.0f;
            r1.x = a10 ? 1.0f : 0.0f; r1.y = a11 ? 1.0f : 0.0f; r1.z = a12 ? 1.0f : 0.0f; r1.w = a13 ? 1.0f : 0.0f;
            r2.x = a20 ? 1.0f : 0.0f; r2.y = a21 ? 1.0f : 0.0f; r2.z = a22 ? 1.0f : 0.0f; r2.w = a23 ? 1.0f : 0.0f;
            r3.x = a30 ? 1.0f : 0.0f; r3.y = a31 ? 1.0f : 0.0f; r3.z = a32 ? 1.0f : 0.0f; r3.w = a33 ? 1.0f : 0.0f;
            __stcs(&o4[i], r0);
            __stcs(&o4[i + gstride], r1);
            __stcs(&o4[i + 2 * gstride], r2);
            __stcs(&o4[i + 3 * gstride], r3);
            below += b00 + b01 + b02 + b03 + b10 + b11 + b12 + b13;
            below += b20 + b21 + b22 + b23 + b30 + b31 + b32 + b33;
            bool c0 = (!a00 && !b00) || (!a01 && !b01) || (!a02 && !b02) || (!a03 && !b03);
            bool c1 = (!a10 && !b10) || (!a11 && !b11) || (!a12 && !b12) || (!a13 && !b13);
            bool c2 = (!a20 && !b20) || (!a21 && !b21) || (!a22 && !b22) || (!a23 && !b23);
            bool c3 = (!a30 && !b30) || (!a31 && !b31) || (!a32 && !b32) || (!a33 && !b33);
            if (c0 | c1 | c2 | c3) {
#pragma unroll
                for (int u = 0; u < 4; u++) {
                    bool cu = (u == 0) ? c0 : (u == 1) ? c1 : (u == 2) ? c2 : c3;
                    if (!cu) continue;
                    float4 v = (u == 0) ? v0 : (u == 1) ? v1 : (u == 2) ? v2 : v3;
                    unsigned e = (unsigned)(i + u * gstride) * 4u;
                    if (!(v.x > fhi) && !(v.x < flo)) {
                        unsigned key = f2key(v.x);
                        unsigned p = atomicAdd(&s_cnt, 1u);
                        if (p < STAGE_CAP) { s_a[p] = key; s_b[p] = e; atomicAdd(&s_h[min((key - klo) >> sh, 2047u)], 1u); }
                    }
                    if (!(v.y > fhi) && !(v.y < flo)) {
                        unsigned key = f2key(v.y);
                        unsigned p = atomicAdd(&s_cnt, 1u);
                        if (p < STAGE_CAP) { s_a[p] = key; s_b[p] = e + 1u; atomicAdd(&s_h[min((key - klo) >> sh, 2047u)], 1u); }
                    }
                    if (!(v.z > fhi) && !(v.z < flo)) {
                        unsigned key = f2key(v.z);
                        unsigned p = atomicAdd(&s_cnt, 1u);
                        if (p < STAGE_CAP) { s_a[p] = key; s_b[p] = e + 2u; atomicAdd(&s_h[min((key - klo) >> sh, 2047u)], 1u); }
                    }
                    if (!(v.w > fhi) && !(v.w < flo)) {
                        unsigned key = f2key(v.w);
                        unsigned p = atomicAdd(&s_cnt, 1u);
                        if (p < STAGE_CAP) { s_a[p] = key; s_b[p] = e + 3u; atomicAdd(&s_h[min((key - klo) >> sh, 2047u)], 1u); }
                    }
                }
            }
        }
        for (; i < n4; i += gstride) {
            float4 v = __ldcs(&x4[i]);
            bool a0 = v.x > fhi, a1 = v.y > fhi, a2 = v.z > fhi, a3 = v.w > fhi;
            bool b0 = v.x < flo, b1 = v.y < flo, b2 = v.z < flo, b3 = v.w < flo;
            float4 rr;
            rr.x = a0 ? 1.0f : 0.0f; rr.y = a1 ? 1.0f : 0.0f;
            rr.z = a2 ? 1.0f : 0.0f; rr.w = a3 ? 1.0f : 0.0f;
            __stcs(&o4[i], rr);
            below += b0 + b1 + b2 + b3;
            unsigned e = (unsigned)i * 4u;
            if (!a0 && !b0) {
                unsigned key = f2key(v.x);
                unsigned p = atomicAdd(&s_cnt, 1u);
                if (p < STAGE_CAP) { s_a[p] = key; s_b[p] = e; atomicAdd(&s_h[min((key - klo) >> sh, 2047u)], 1u); }
            }
            if (!a1 && !b1) {
                unsigned key = f2key(v.y);
                unsigned p = atomicAdd(&s_cnt, 1u);
                if (p < STAGE_CAP) { s_a[p] = key; s_b[p] = e + 1u; atomicAdd(&s_h[min((key - klo) >> sh, 2047u)], 1u); }
            }
            if (!a2 && !b2) {
                unsigned key = f2key(v.z);
                unsigned p = atomicAdd(&s_cnt, 1u);
                if (p < STAGE_CAP) { s_a[p] = key; s_b[p] = e + 2u; atomicAdd(&s_h[min((key - klo) >> sh, 2047u)], 1u); }
            }
            if (!a3 && !b3) {
                unsigned key = f2key(v.w);
                unsigned p = atomicAdd(&s_cnt, 1u);
                if (p < STAGE_CAP) { s_a[p] = key; s_b[p] = e + 3u; atomicAdd(&s_h[min((key - klo) >> sh, 2047u)], 1u); }
            }
        }
#pragma unroll
        for (int off = 16; off > 0; off >>= 1)
            below += __shfl_down_sync(0xffffffffu, below, off);
        if ((tid & 31) == 0) atomicAdd(&s_below, below);
        __syncthreads();
        unsigned cnt = s_cnt < STAGE_CAP ? s_cnt : STAGE_CAP;
        if (tid == 0) {
            if (s_cnt > STAGE_CAP) atomicExch(&g_overflow, 1u);
            atomicAdd(&g_below, s_below);
            s_base = atomicAdd(&g_count, cnt);
        }
        __syncthreads();
        unsigned base = s_base;
        for (unsigned j = tid; j < cnt; j += BLOCK) {
            g_cand[base + j] = s_a[j];
            g_cidx[base + j] = s_b[j];
        }
        for (int j = tid; j < 2048; j += BLOCK)
            if (s_h[j]) atomicAdd(&g_hist2048[j], s_h[j]);
        // scalar tail (n % 4), block 0 only
        if (bid == 0) {
            for (int j = (n & ~3) + tid; j < n; j += BLOCK) {
                float v = x[j];
                bool a = v > fhi, b = v < flo;
                out[j] = a ? 1.0f : 0.0f;
                if (b) atomicAdd(&g_below, 1u);
                else if (!a) {
                    unsigned key = f2key(v);
                    unsigned p = atomicAdd(&g_count, 1u);
                    if (p < CAND_CAP) {
                        g_cand[p] = key; g_cidx[p] = (unsigned)j;
                        atomicAdd(&g_hist2048[min((key - klo) >> sh, 2047u)], 1u);
                    } else atomicExch(&g_overflow, 1u);
                }
            }
        }
    }
    gsync(G);

    // ---- Phase D: level-1 select (local) + level-2 candidate hist ----
    unsigned nc, ok, b2base = 0u, rank2 = 0u, w = 1u;
    {
        for (int i = tid; i < 2048; i += BLOCK) s_h[i] = g_hist2048[i];
        unsigned below_g = g_below;
        nc = g_count;
        unsigned ovf = g_overflow;
        ok = pickok && (!ovf) && (idx >= below_g) && ((idx - below_g) < nc) && (nc <= CAND_CAP);
        if (tid == 0) s_obin = 0xffffffffu;
        __syncthreads();
        if (ok) {
            bsel(s_h, 2048, idx - below_g, &s_obin, &s_orank, s_wofs);
            if (s_obin == 0xffffffffu) ok = 0u;
            else {
                b2base = klo + (s_obin << sh);
                rank2 = s_orank;
                w = 1u << sh;
                for (int i = tid; i < 2048; i += BLOCK) s_a[i] = 0u;
                __syncthreads();
                for (unsigned i = bid * BLOCK + tid; i < nc; i += (unsigned)gstride) {
                    unsigned off = g_cand[i] - b2base;
                    if (off < w) atomicAdd(&s_a[min(off, 2047u)], 1u);
                }
                __syncthreads();
                unsigned wcap = w < 2048u ? w : 2048u;
                for (unsigned i = tid; i < wcap; i += BLOCK)
                    if (s_a[i]) atomicAdd(&g_hist2b[i], s_a[i]);
            }
        }
        // zero sample hists for next replay (C1 consumers are all past gsync)
        for (int i = bid * BLOCK + tid; i < 2048; i += gstride) g_fine[i] = 0u;
        for (int i = bid * BLOCK + tid; i < 256; i += gstride) g_coarse[i] = 0u;
    }
    gsync(G);

    // ---- Phase E: threshold select (local) + cleanup + fixup ----
    {
        for (int i = tid; i < 2048; i += BLOCK) s_h[i] = g_hist2b[i];
        if (tid == 0) s_obin = 0xffffffffu;
        __syncthreads();
        float thr = __int_as_float(0x7f800000);
        if (ok) {
            int nb = (int)(w < 2048u ? w : 2048u);
            bsel(s_h, nb, rank2, &s_obin, &s_orank, s_wofs);
            if (s_obin == 0xffffffffu) ok = 0u;
            else thr = key2f(b2base + s_obin);
        }
        gsync(G);
        for (int i = bid * BLOCK + tid; i < 2048; i += gstride) {
            g_hist2048[i] = 0u;
            g_hist2b[i] = 0u;
        }
        if (bid == 0 && tid == 0) {
            g_below = 0u; g_count = 0u; g_overflow = 0u;
        }
        if (ok) {
            for (unsigned i = bid * BLOCK + tid; i < nc; i += (unsigned)gstride)
                if (key2f(g_cand[i]) >= thr) out[g_cidx[i]] = 1.0f;
        }
    }

    // ---- Fallback phases (grid-uniform: every block computed the same ok) ----
    if (!ok) {
        for (int i = bid * BLOCK + tid; i < 65536; i += gstride) g_hist64k[i] = 0u;
        gsync(G);
        for (int i = bid * BLOCK + tid; i < n; i += gstride)
            atomicAdd(&g_hist64k[f2key(x[i]) >> 16], 1u);
        gsync(G);
        unsigned fb = 0u, fr = 0u;
        {
            unsigned ob, orr;
            sel64k(g_hist64k, idx, &ob, &orr, s_h, s_a, s_wofs, &s_obin, &s_orank);
            fb = ob; fr = orr;
        }
        gsync(G);
        for (int i = bid * BLOCK + tid; i < 65536; i += gstride) g_hist64k[i] = 0u;
        gsync(G);
        if (fb != 0xffffffffu) {
            for (int i = bid * BLOCK + tid; i < n; i += gstride) {
                unsigned key = f2key(x[i]);
                if ((key >> 16) == fb) atomicAdd(&g_hist64k[key & 0xffffu], 1u);
            }
        }
        gsync(G);
        float thr2 = __int_as_float(0x7f800000);
        if (fb != 0xffffffffu) {
            unsigned ob, orr;
            sel64k(g_hist64k, fr, &ob, &orr, s_h, s_a, s_wofs, &s_obin, &s_orank);
            if (ob != 0xffffffffu) thr2 = key2f((fb << 16) | ob);
        }
        for (int i = bid * BLOCK + tid; i < n; i += gstride)
            out[i] = (x[i] >= thr2) ? 1.0f : 0.0f;
    }
}

__global__ void k_fill0(float* __restrict__ out, int n) {
    const int stride = gridDim.x * blockDim.x;
    for (int i = blockIdx.x * blockDim.x + threadIdx.x; i < n; i += stride)
        out[i] = 0.0f;
}

extern "C" void kernel_launch(void* const* d_in, const int* in_sizes, int n_in,
                              void* d_out, int out_size) {
    const float* x = (const float*)d_in[0];
    float* out = (float*)d_out;
    const long long n = (long long)in_sizes[0];
    const long long k = (long long)((double)n * 0.9);
    if (k <= 0) { k_fill0<<<1184, 256>>>(out, (int)n); return; }
    const unsigned idx = (unsigned)(n - k);   // 0-indexed ascending rank
    const int n4 = (int)(n >> 2);
    // sampled count: first 64 float4s of each 1024-float4 chunk (1/16)
    const long long full = n4 / 1024, rem = n4 % 1024;
    const long long m4 = full * 64 + (rem < 64 ? rem : 64);
    const long long m = m4 * 4;
    unsigned t_target = 0u;
    if (m > 0) {
        t_target = (unsigned)((double)idx * (double)m / (double)n);
        if (t_target >= (unsigned)m) t_target = (unsigned)m - 1u;
    }

    int sm = 148, occ = 6, dev = 0;
    cudaGetDevice(&dev);
    cudaDeviceGetAttribute(&sm, cudaDevAttrMultiProcessorCount, dev);
    cudaOccupancyMaxActiveBlocksPerMultiprocessor(&occ, k_fused, BLOCK, 0);
    if (occ > 6) occ = 6;
    if (occ < 1) occ = 1;
    int G = sm * occ;
    if (G > MAXG) G = MAXG;
    if (G < 1) G = 1;

    k_fused<<<G, BLOCK>>>((const float4*)x, n4, x, (int)n, out, idx, t_target, G);
}